// round 1
// baseline (speedup 1.0000x reference)
#include <cuda_runtime.h>

// LSTM: B=65536, T=28, I=28, H=64, O=10
// out[B,10] = (final hidden h_T) @ W_out^T + b_out
//
// One block handles B_TILE=64 batch rows for all T timesteps.
// Shared memory holds transposed weights, bias, current h (transposed,
// padded stride), and the per-timestep x tile. Each thread owns an
// 8-batch x 2-unit x 4-gate fp32 accumulator tile (64 regs) plus c state.

#define B_TOTAL   65536
#define T_STEPS   28
#define I_DIM     28
#define H_DIM     64
#define G4        256      // 4*H
#define O_DIM     10
#define B_TILE    64
#define HS_STRIDE 68       // padded row stride for h_s / x_s (mult of 4, !=64 to break bank pattern)
#define NTHREADS  256

__device__ __forceinline__ float sigf(float x) { return 1.0f / (1.0f + __expf(-x)); }

__global__ __launch_bounds__(NTHREADS, 1)
void lstm_fused_kernel(const float* __restrict__ x,
                       const float* __restrict__ W_ih,
                       const float* __restrict__ W_hh,
                       const float* __restrict__ b_ih,
                       const float* __restrict__ b_hh,
                       const float* __restrict__ W_out,
                       const float* __restrict__ b_out,
                       float* __restrict__ out)
{
    extern __shared__ float sm[];
    float* Wih_s  = sm;                          // [I_DIM][G4]  transposed: Wih_s[i][row]
    float* Whh_s  = Wih_s + I_DIM * G4;          // [H_DIM][G4]  transposed: Whh_s[k][row]
    float* bias_s = Whh_s + H_DIM * G4;          // [G4]
    float* Wout_s = bias_s + G4;                 // [O_DIM][H_DIM]
    float* bout_s = Wout_s + O_DIM * H_DIM;      // [16]
    float* h_s    = bout_s + 16;                 // [H_DIM][HS_STRIDE]   h_s[k][b]
    float* x_s    = h_s + H_DIM * HS_STRIDE;     // [I_DIM][HS_STRIDE]   x_s[i][b]

    const int tx = threadIdx.x;
    const int b0 = blockIdx.x * B_TILE;

    // ---- stage weights into shared (transposed so k/i index the row) ----
    for (int idx = tx; idx < G4 * I_DIM; idx += NTHREADS) {
        int row = idx / I_DIM, i = idx % I_DIM;
        Wih_s[i * G4 + row] = W_ih[idx];
    }
    for (int idx = tx; idx < G4 * H_DIM; idx += NTHREADS) {
        int row = idx >> 6, k = idx & 63;
        Whh_s[k * G4 + row] = W_hh[idx];
    }
    for (int idx = tx; idx < G4; idx += NTHREADS)
        bias_s[idx] = b_ih[idx] + b_hh[idx];
    for (int idx = tx; idx < O_DIM * H_DIM; idx += NTHREADS)
        Wout_s[idx] = W_out[idx];
    if (tx < O_DIM) bout_s[tx] = b_out[tx];
    for (int idx = tx; idx < H_DIM * HS_STRIDE; idx += NTHREADS)
        h_s[idx] = 0.0f;

    // thread tile: 8 batch rows, 2 hidden units (all 4 gates)
    const int bsub = (tx & 7) * 8;        // local batch base: 0..56
    const int usub = (tx >> 3) * 2;       // unit base: 0..62

    float c[8][2];
#pragma unroll
    for (int b = 0; b < 8; ++b) { c[b][0] = 0.0f; c[b][1] = 0.0f; }

    for (int t = 0; t < T_STEPS; ++t) {
        // stage x[:, t, :] tile (transposed to x_s[i][b])
        for (int idx = tx; idx < B_TILE * I_DIM; idx += NTHREADS) {
            int b = idx / I_DIM, i = idx % I_DIM;
            x_s[i * HS_STRIDE + b] =
                x[(size_t)(b0 + b) * (T_STEPS * I_DIM) + t * I_DIM + i];
        }
        __syncthreads();   // x ready; previous h_s writes visible

        float acc[8][2][4];
#pragma unroll
        for (int g = 0; g < 4; ++g) {
            float bi0 = bias_s[g * H_DIM + usub];
            float bi1 = bias_s[g * H_DIM + usub + 1];
#pragma unroll
            for (int b = 0; b < 8; ++b) { acc[b][0][g] = bi0; acc[b][1][g] = bi1; }
        }

        // ---- input contribution: sum_i x[b][i] * W_ih[row][i] ----
        for (int i = 0; i < I_DIM; ++i) {
            const float* xr = x_s + i * HS_STRIDE + bsub;
            float4 xv0 = *(const float4*)xr;
            float4 xv1 = *(const float4*)(xr + 4);
            float xb[8] = {xv0.x, xv0.y, xv0.z, xv0.w, xv1.x, xv1.y, xv1.z, xv1.w};
            const float* wr = Wih_s + i * G4 + usub;
#pragma unroll
            for (int g = 0; g < 4; ++g) {
                float2 w = *(const float2*)(wr + g * H_DIM);
#pragma unroll
                for (int b = 0; b < 8; ++b) {
                    acc[b][0][g] = fmaf(xb[b], w.x, acc[b][0][g]);
                    acc[b][1][g] = fmaf(xb[b], w.y, acc[b][1][g]);
                }
            }
        }

        // ---- recurrent contribution: sum_k h[b][k] * W_hh[row][k] ----
        for (int k = 0; k < H_DIM; ++k) {
            const float* hr = h_s + k * HS_STRIDE + bsub;
            float4 hv0 = *(const float4*)hr;
            float4 hv1 = *(const float4*)(hr + 4);
            float hb[8] = {hv0.x, hv0.y, hv0.z, hv0.w, hv1.x, hv1.y, hv1.z, hv1.w};
            const float* wr = Whh_s + k * G4 + usub;
#pragma unroll
            for (int g = 0; g < 4; ++g) {
                float2 w = *(const float2*)(wr + g * H_DIM);
#pragma unroll
                for (int b = 0; b < 8; ++b) {
                    acc[b][0][g] = fmaf(hb[b], w.x, acc[b][0][g]);
                    acc[b][1][g] = fmaf(hb[b], w.y, acc[b][1][g]);
                }
            }
        }
        __syncthreads();   // all reads of h_s done before overwrite

        // ---- gates, c/h update (PyTorch gate order: i, f, g, o) ----
#pragma unroll
        for (int uu = 0; uu < 2; ++uu) {
#pragma unroll
            for (int b = 0; b < 8; ++b) {
                float ig = sigf(acc[b][uu][0]);
                float fg = sigf(acc[b][uu][1]);
                float gg = tanhf(acc[b][uu][2]);
                float og = sigf(acc[b][uu][3]);
                float cn = fg * c[b][uu] + ig * gg;
                c[b][uu] = cn;
                h_s[(usub + uu) * HS_STRIDE + bsub + b] = og * tanhf(cn);
            }
        }
    }
    __syncthreads();   // final h_s ready

    // ---- output projection: out[b][o] = sum_k h[b][k] * W_out[o][k] + b_out[o] ----
    for (int idx = tx; idx < B_TILE * O_DIM; idx += NTHREADS) {
        int b = idx / O_DIM, o = idx % O_DIM;
        float s = bout_s[o];
#pragma unroll 8
        for (int k = 0; k < H_DIM; ++k)
            s = fmaf(h_s[k * HS_STRIDE + b], Wout_s[o * H_DIM + k], s);
        out[(size_t)(b0 + b) * O_DIM + o] = s;
    }
}

extern "C" void kernel_launch(void* const* d_in, const int* in_sizes, int n_in,
                              void* d_out, int out_size)
{
    const float* x     = (const float*)d_in[0];
    const float* W_ih  = (const float*)d_in[1];
    const float* W_hh  = (const float*)d_in[2];
    const float* b_ih  = (const float*)d_in[3];
    const float* b_hh  = (const float*)d_in[4];
    const float* W_out = (const float*)d_in[5];
    const float* b_out = (const float*)d_in[6];
    float* out = (float*)d_out;

    const size_t smem_floats =
        (size_t)I_DIM * G4 + (size_t)H_DIM * G4 + G4 + O_DIM * H_DIM + 16 +
        (size_t)H_DIM * HS_STRIDE + (size_t)I_DIM * HS_STRIDE;   // 30720 floats
    const size_t smem_bytes = smem_floats * sizeof(float);       // 122880 B

    cudaFuncSetAttribute(lstm_fused_kernel,
                         cudaFuncAttributeMaxDynamicSharedMemorySize,
                         (int)smem_bytes);

    lstm_fused_kernel<<<B_TOTAL / B_TILE, NTHREADS, smem_bytes>>>(
        x, W_ih, W_hh, b_ih, b_hh, W_out, b_out, out);
}

// round 2
// speedup vs baseline: 1.0409x; 1.0409x over previous
#include <cuda_runtime.h>

// LSTM: B=65536, T=28, I=28, H=64, O=10
// Round 2: packed fma.rn.f32x2 (FFMA2) along the batch dimension.
// One block = 64 batch rows, 256 threads, thread tile 8 batch x 2 units x 4 gates.
// Accumulators are 32 packed f32x2 registers (batch pairs).

#define B_TOTAL   65536
#define T_STEPS   28
#define I_DIM     28
#define H_DIM     64
#define G4        256      // 4*H
#define O_DIM     10
#define B_TILE    64
#define HS_STRIDE 68       // padded row stride for h_s / x_s
#define NTHREADS  256

typedef unsigned long long ull;

__device__ __forceinline__ void fma2(ull& acc, ull a, ull b) {
    asm("fma.rn.f32x2 %0, %1, %2, %0;" : "+l"(acc) : "l"(a), "l"(b));
}
__device__ __forceinline__ ull pack2(float lo, float hi) {
    ull r; asm("mov.b64 %0, {%1, %2};" : "=l"(r) : "f"(lo), "f"(hi)); return r;
}
__device__ __forceinline__ float2 unpack2(ull v) {
    float2 r; asm("mov.b64 {%0, %1}, %2;" : "=f"(r.x), "=f"(r.y) : "l"(v)); return r;
}
__device__ __forceinline__ float sigf(float x) { return 1.0f / (1.0f + __expf(-x)); }

__global__ __launch_bounds__(NTHREADS, 1)
void lstm_fused_kernel(const float* __restrict__ x,
                       const float* __restrict__ W_ih,
                       const float* __restrict__ W_hh,
                       const float* __restrict__ b_ih,
                       const float* __restrict__ b_hh,
                       const float* __restrict__ W_out,
                       const float* __restrict__ b_out,
                       float* __restrict__ out)
{
    extern __shared__ float sm[];
    float* Wih_s  = sm;                          // [I_DIM][G4]  Wih_s[i][row]
    float* Whh_s  = Wih_s + I_DIM * G4;          // [H_DIM][G4]  Whh_s[k][row]
    float* bias_s = Whh_s + H_DIM * G4;          // [G4]
    float* Wout_s = bias_s + G4;                 // [O_DIM][H_DIM]
    float* bout_s = Wout_s + O_DIM * H_DIM;      // [16]
    float* h_s    = bout_s + 16;                 // [H_DIM][HS_STRIDE]
    float* x_s    = h_s + H_DIM * HS_STRIDE;     // [I_DIM][HS_STRIDE]

    const int tx = threadIdx.x;
    const int b0 = blockIdx.x * B_TILE;

    // ---- stage weights (transposed so k/i index the row) ----
    for (int idx = tx; idx < G4 * I_DIM; idx += NTHREADS) {
        int row = idx / I_DIM, i = idx % I_DIM;
        Wih_s[i * G4 + row] = W_ih[idx];
    }
    for (int idx = tx; idx < G4 * H_DIM; idx += NTHREADS) {
        int row = idx >> 6, k = idx & 63;
        Whh_s[k * G4 + row] = W_hh[idx];
    }
    for (int idx = tx; idx < G4; idx += NTHREADS)
        bias_s[idx] = b_ih[idx] + b_hh[idx];
    for (int idx = tx; idx < O_DIM * H_DIM; idx += NTHREADS)
        Wout_s[idx] = W_out[idx];
    if (tx < O_DIM) bout_s[tx] = b_out[tx];
    for (int idx = tx; idx < H_DIM * HS_STRIDE; idx += NTHREADS)
        h_s[idx] = 0.0f;

    const int bsub = (tx & 7) * 8;        // local batch base 0..56
    const int usub = (tx >> 3) * 2;       // unit base 0..62

    float c[8][2];
#pragma unroll
    for (int b = 0; b < 8; ++b) { c[b][0] = 0.0f; c[b][1] = 0.0f; }

    // packed bias per (u,g), invariant across t
    ull bias_p[2][4];
#pragma unroll
    for (int uu = 0; uu < 2; ++uu)
#pragma unroll
        for (int g = 0; g < 4; ++g) {
            float bv = bias_s[g * H_DIM + usub + uu];
            bias_p[uu][g] = pack2(bv, bv);
        }

    for (int t = 0; t < T_STEPS; ++t) {
        // stage x[:, t, :] tile (transposed to x_s[i][b])
        for (int idx = tx; idx < B_TILE * I_DIM; idx += NTHREADS) {
            int b = idx / I_DIM, i = idx % I_DIM;
            x_s[i * HS_STRIDE + b] =
                x[(size_t)(b0 + b) * (T_STEPS * I_DIM) + t * I_DIM + i];
        }
        __syncthreads();   // x ready; previous h_s writes visible

        // acc[bp][uu][g] : batch pair bp covers local batches (2bp, 2bp+1)
        ull acc[4][2][4];
#pragma unroll
        for (int bp = 0; bp < 4; ++bp)
#pragma unroll
            for (int uu = 0; uu < 2; ++uu)
#pragma unroll
                for (int g = 0; g < 4; ++g)
                    acc[bp][uu][g] = bias_p[uu][g];

        // ---- input contribution ----
        for (int i = 0; i < I_DIM; ++i) {
            const float* xr = x_s + i * HS_STRIDE + bsub;
            ulonglong2 xa = *(const ulonglong2*)xr;
            ulonglong2 xb = *(const ulonglong2*)(xr + 4);
            ull xp[4] = {xa.x, xa.y, xb.x, xb.y};
            const float* wr = Wih_s + i * G4 + usub;
#pragma unroll
            for (int g = 0; g < 4; ++g) {
                float2 w = *(const float2*)(wr + g * H_DIM);
                ull w0 = pack2(w.x, w.x);
                ull w1 = pack2(w.y, w.y);
#pragma unroll
                for (int bp = 0; bp < 4; ++bp) {
                    fma2(acc[bp][0][g], xp[bp], w0);
                    fma2(acc[bp][1][g], xp[bp], w1);
                }
            }
        }

        // ---- recurrent contribution ----
        for (int k = 0; k < H_DIM; ++k) {
            const float* hr = h_s + k * HS_STRIDE + bsub;
            ulonglong2 ha = *(const ulonglong2*)hr;
            ulonglong2 hb = *(const ulonglong2*)(hr + 4);
            ull hp[4] = {ha.x, ha.y, hb.x, hb.y};
            const float* wr = Whh_s + k * G4 + usub;
#pragma unroll
            for (int g = 0; g < 4; ++g) {
                float2 w = *(const float2*)(wr + g * H_DIM);
                ull w0 = pack2(w.x, w.x);
                ull w1 = pack2(w.y, w.y);
#pragma unroll
                for (int bp = 0; bp < 4; ++bp) {
                    fma2(acc[bp][0][g], hp[bp], w0);
                    fma2(acc[bp][1][g], hp[bp], w1);
                }
            }
        }
        __syncthreads();   // all reads of h_s done before overwrite

        // ---- gates + state update (gate order i,f,g,o) ----
#pragma unroll
        for (int uu = 0; uu < 2; ++uu) {
            float hnew[8];
#pragma unroll
            for (int bp = 0; bp < 4; ++bp) {
                float2 iv = unpack2(acc[bp][uu][0]);
                float2 fv = unpack2(acc[bp][uu][1]);
                float2 gv = unpack2(acc[bp][uu][2]);
                float2 ov = unpack2(acc[bp][uu][3]);

                float ig0 = sigf(iv.x), ig1 = sigf(iv.y);
                float fg0 = sigf(fv.x), fg1 = sigf(fv.y);
                float gg0 = tanhf(gv.x), gg1 = tanhf(gv.y);
                float og0 = sigf(ov.x), og1 = sigf(ov.y);

                float c0 = fg0 * c[2*bp][uu]   + ig0 * gg0;
                float c1 = fg1 * c[2*bp+1][uu] + ig1 * gg1;
                c[2*bp][uu]   = c0;
                c[2*bp+1][uu] = c1;
                hnew[2*bp]   = og0 * tanhf(c0);
                hnew[2*bp+1] = og1 * tanhf(c1);
            }
            float* hw = h_s + (usub + uu) * HS_STRIDE + bsub;
            *(float4*)hw       = make_float4(hnew[0], hnew[1], hnew[2], hnew[3]);
            *(float4*)(hw + 4) = make_float4(hnew[4], hnew[5], hnew[6], hnew[7]);
        }
    }
    __syncthreads();   // final h_s ready

    // ---- output projection ----
    for (int idx = tx; idx < B_TILE * O_DIM; idx += NTHREADS) {
        int b = idx / O_DIM, o = idx % O_DIM;
        float s = bout_s[o];
#pragma unroll 8
        for (int k = 0; k < H_DIM; ++k)
            s = fmaf(h_s[k * HS_STRIDE + b], Wout_s[o * H_DIM + k], s);
        out[(size_t)(b0 + b) * O_DIM + o] = s;
    }
}

extern "C" void kernel_launch(void* const* d_in, const int* in_sizes, int n_in,
                              void* d_out, int out_size)
{
    const float* x     = (const float*)d_in[0];
    const float* W_ih  = (const float*)d_in[1];
    const float* W_hh  = (const float*)d_in[2];
    const float* b_ih  = (const float*)d_in[3];
    const float* b_hh  = (const float*)d_in[4];
    const float* W_out = (const float*)d_in[5];
    const float* b_out = (const float*)d_in[6];
    float* out = (float*)d_out;

    const size_t smem_floats =
        (size_t)I_DIM * G4 + (size_t)H_DIM * G4 + G4 + O_DIM * H_DIM + 16 +
        (size_t)H_DIM * HS_STRIDE + (size_t)I_DIM * HS_STRIDE;
    const size_t smem_bytes = smem_floats * sizeof(float);   // 122880 B

    cudaFuncSetAttribute(lstm_fused_kernel,
                         cudaFuncAttributeMaxDynamicSharedMemorySize,
                         (int)smem_bytes);

    lstm_fused_kernel<<<B_TOTAL / B_TILE, NTHREADS, smem_bytes>>>(
        x, W_ih, W_hh, b_ih, b_hh, W_out, b_out, out);
}

// round 4
// speedup vs baseline: 1.2474x; 1.1984x over previous
#include <cuda_runtime.h>

// LSTM: B=65536, T=28, I=28, H=64, O=10
// Round 4: Round-3 design (512 threads / 16 warps per CTA, 4 batch x 2 unit
// x 4 gate FFMA2 thread tiles) + the missing __syncthreads() between weight
// staging and the hoisted bias_p precompute (R3's rel_err 5e-3 was that race).

#define B_TOTAL   65536
#define T_STEPS   28
#define I_DIM     28
#define H_DIM     64
#define G4        256      // 4*H
#define O_DIM     10
#define B_TILE    64
#define HS_STRIDE 68       // padded row stride for h_s / x_s (16B-aligned rows)
#define NTHREADS  512

typedef unsigned long long ull;

__device__ __forceinline__ void fma2(ull& acc, ull a, ull b) {
    asm("fma.rn.f32x2 %0, %1, %2, %0;" : "+l"(acc) : "l"(a), "l"(b));
}
__device__ __forceinline__ ull pack2(float lo, float hi) {
    ull r; asm("mov.b64 %0, {%1, %2};" : "=l"(r) : "f"(lo), "f"(hi)); return r;
}
__device__ __forceinline__ float2 unpack2(ull v) {
    float2 r; asm("mov.b64 {%0, %1}, %2;" : "=f"(r.x), "=f"(r.y) : "l"(v)); return r;
}
__device__ __forceinline__ float sigf(float x) { return 1.0f / (1.0f + __expf(-x)); }

__global__ __launch_bounds__(NTHREADS, 1)
void lstm_fused_kernel(const float* __restrict__ x,
                       const float* __restrict__ W_ih,
                       const float* __restrict__ W_hh,
                       const float* __restrict__ b_ih,
                       const float* __restrict__ b_hh,
                       const float* __restrict__ W_out,
                       const float* __restrict__ b_out,
                       float* __restrict__ out)
{
    extern __shared__ float sm[];
    float* Wih_s  = sm;                          // [I_DIM][G4]  Wih_s[i][row]
    float* Whh_s  = Wih_s + I_DIM * G4;          // [H_DIM][G4]  Whh_s[k][row]
    float* bias_s = Whh_s + H_DIM * G4;          // [G4]
    float* Wout_s = bias_s + G4;                 // [O_DIM][H_DIM]
    float* bout_s = Wout_s + O_DIM * H_DIM;      // [16]
    float* h_s    = bout_s + 16;                 // [H_DIM][HS_STRIDE]
    float* x_s    = h_s + H_DIM * HS_STRIDE;     // [I_DIM][HS_STRIDE]

    const int tx = threadIdx.x;
    const int b0 = blockIdx.x * B_TILE;

    // ---- stage weights (transposed so k/i index the row) ----
    for (int idx = tx; idx < G4 * I_DIM; idx += NTHREADS) {
        int row = idx / I_DIM, i = idx % I_DIM;
        Wih_s[i * G4 + row] = W_ih[idx];
    }
    for (int idx = tx; idx < G4 * H_DIM; idx += NTHREADS) {
        int row = idx >> 6, k = idx & 63;
        Whh_s[k * G4 + row] = W_hh[idx];
    }
    for (int idx = tx; idx < G4; idx += NTHREADS)
        bias_s[idx] = b_ih[idx] + b_hh[idx];
    for (int idx = tx; idx < O_DIM * H_DIM; idx += NTHREADS)
        Wout_s[idx] = W_out[idx];
    if (tx < O_DIM) bout_s[tx] = b_out[tx];
    for (int idx = tx; idx < H_DIM * HS_STRIDE; idx += NTHREADS)
        h_s[idx] = 0.0f;

    __syncthreads();   // <<< R4 fix: staging visible before bias_p reads

    // thread tile: 4 batch rows (one 16B vector), 2 hidden units, all 4 gates
    const int bsub = (tx & 15) * 4;       // local batch base 0..60
    const int usub = (tx >> 4) * 2;       // unit base 0..62

    float c[4][2];
#pragma unroll
    for (int b = 0; b < 4; ++b) { c[b][0] = 0.0f; c[b][1] = 0.0f; }

    // packed bias per (u,g), invariant across t
    ull bias_p[2][4];
#pragma unroll
    for (int uu = 0; uu < 2; ++uu)
#pragma unroll
        for (int g = 0; g < 4; ++g) {
            float bv = bias_s[g * H_DIM + usub + uu];
            bias_p[uu][g] = pack2(bv, bv);
        }

    for (int t = 0; t < T_STEPS; ++t) {
        // stage x[:, t, :] tile (transposed to x_s[i][b])
        for (int idx = tx; idx < B_TILE * I_DIM; idx += NTHREADS) {
            int b = idx / I_DIM, i = idx % I_DIM;
            x_s[i * HS_STRIDE + b] =
                x[(size_t)(b0 + b) * (T_STEPS * I_DIM) + t * I_DIM + i];
        }
        __syncthreads();   // x ready; previous h_s writes visible

        // acc[bp][uu][g] : batch pair bp covers local batches (2bp, 2bp+1)
        ull acc[2][2][4];
#pragma unroll
        for (int bp = 0; bp < 2; ++bp)
#pragma unroll
            for (int uu = 0; uu < 2; ++uu)
#pragma unroll
                for (int g = 0; g < 4; ++g)
                    acc[bp][uu][g] = bias_p[uu][g];

        // ---- input contribution ----
#pragma unroll 4
        for (int i = 0; i < I_DIM; ++i) {
            ulonglong2 xa = *(const ulonglong2*)(x_s + i * HS_STRIDE + bsub);
            const float* wr = Wih_s + i * G4 + usub;
#pragma unroll
            for (int g = 0; g < 4; ++g) {
                float2 w = *(const float2*)(wr + g * H_DIM);
                ull w0 = pack2(w.x, w.x);
                ull w1 = pack2(w.y, w.y);
                fma2(acc[0][0][g], xa.x, w0);
                fma2(acc[1][0][g], xa.y, w0);
                fma2(acc[0][1][g], xa.x, w1);
                fma2(acc[1][1][g], xa.y, w1);
            }
        }

        // ---- recurrent contribution ----
#pragma unroll 4
        for (int k = 0; k < H_DIM; ++k) {
            ulonglong2 ha = *(const ulonglong2*)(h_s + k * HS_STRIDE + bsub);
            const float* wr = Whh_s + k * G4 + usub;
#pragma unroll
            for (int g = 0; g < 4; ++g) {
                float2 w = *(const float2*)(wr + g * H_DIM);
                ull w0 = pack2(w.x, w.x);
                ull w1 = pack2(w.y, w.y);
                fma2(acc[0][0][g], ha.x, w0);
                fma2(acc[1][0][g], ha.y, w0);
                fma2(acc[0][1][g], ha.x, w1);
                fma2(acc[1][1][g], ha.y, w1);
            }
        }
        __syncthreads();   // all reads of h_s done before overwrite

        // ---- gates + state update (gate order i,f,g,o) ----
#pragma unroll
        for (int uu = 0; uu < 2; ++uu) {
            float hnew[4];
#pragma unroll
            for (int bp = 0; bp < 2; ++bp) {
                float2 iv = unpack2(acc[bp][uu][0]);
                float2 fv = unpack2(acc[bp][uu][1]);
                float2 gv = unpack2(acc[bp][uu][2]);
                float2 ov = unpack2(acc[bp][uu][3]);

                float ig0 = sigf(iv.x), ig1 = sigf(iv.y);
                float fg0 = sigf(fv.x), fg1 = sigf(fv.y);
                float gg0 = tanhf(gv.x), gg1 = tanhf(gv.y);
                float og0 = sigf(ov.x), og1 = sigf(ov.y);

                float c0 = fg0 * c[2*bp][uu]   + ig0 * gg0;
                float c1 = fg1 * c[2*bp+1][uu] + ig1 * gg1;
                c[2*bp][uu]   = c0;
                c[2*bp+1][uu] = c1;
                hnew[2*bp]   = og0 * tanhf(c0);
                hnew[2*bp+1] = og1 * tanhf(c1);
            }
            *(float4*)(h_s + (usub + uu) * HS_STRIDE + bsub) =
                make_float4(hnew[0], hnew[1], hnew[2], hnew[3]);
        }
    }
    __syncthreads();   // final h_s ready

    // ---- output projection ----
    for (int idx = tx; idx < B_TILE * O_DIM; idx += NTHREADS) {
        int b = idx / O_DIM, o = idx % O_DIM;
        float s = bout_s[o];
#pragma unroll 8
        for (int k = 0; k < H_DIM; ++k)
            s = fmaf(h_s[k * HS_STRIDE + b], Wout_s[o * H_DIM + k], s);
        out[(size_t)(b0 + b) * O_DIM + o] = s;
    }
}

extern "C" void kernel_launch(void* const* d_in, const int* in_sizes, int n_in,
                              void* d_out, int out_size)
{
    const float* x     = (const float*)d_in[0];
    const float* W_ih  = (const float*)d_in[1];
    const float* W_hh  = (const float*)d_in[2];
    const float* b_ih  = (const float*)d_in[3];
    const float* b_hh  = (const float*)d_in[4];
    const float* W_out = (const float*)d_in[5];
    const float* b_out = (const float*)d_in[6];
    float* out = (float*)d_out;

    const size_t smem_floats =
        (size_t)I_DIM * G4 + (size_t)H_DIM * G4 + G4 + O_DIM * H_DIM + 16 +
        (size_t)H_DIM * HS_STRIDE + (size_t)I_DIM * HS_STRIDE;
    const size_t smem_bytes = smem_floats * sizeof(float);   // 122880 B

    cudaFuncSetAttribute(lstm_fused_kernel,
                         cudaFuncAttributeMaxDynamicSharedMemorySize,
                         (int)smem_bytes);

    lstm_fused_kernel<<<B_TOTAL / B_TILE, NTHREADS, smem_bytes>>>(
        x, W_ih, W_hh, b_ih, b_hh, W_out, b_out, out);
}

// round 7
// speedup vs baseline: 3.0125x; 2.4151x over previous
#include <cuda_runtime.h>
#include <cuda_bf16.h>
#include <cstdint>

// LSTM via mma.sync (HMMA). B=65536, T=28, I=28, H=64, O=10.
// Per CTA: 128 batch rows. Per timestep: D[128,256] = A[128,96] @ W[256,96]^T
//   A cols: k 0..63 = h (bf16 hi/lo split), 64..91 = x_t (split), 92 = 1.0, 93..95 = 0
//   B rows: n = gate*64+unit, k as above with W_hh / W_ih / bias.
// 3-pass split precision: D = Ah@Bh + Ah@Bl + Al@Bh  (err ~2^-16).
// R7 fix: B fragments use NON-transposed ldmatrix ([n][k] smem with k contiguous
// already gives k-pairs per thread, which is the mma B fragment layout).

#define T_STEPS  28
#define I_DIM    28
#define H_DIM    64
#define O_DIM    10
#define M_TILE   128
#define NTHREADS 256
#define B_TOTAL  65536

#define KSTRIDE  104                  // bf16 elems per row (208 B, LDSM conflict-free)
#define ROWB     (KSTRIDE * 2)        // 208 bytes

// smem byte offsets
#define A0_HI 0
#define A0_LO (A0_HI + M_TILE * ROWB)      // 26624
#define A1_HI (A0_LO + M_TILE * ROWB)      // 53248
#define A1_LO (A1_HI + M_TILE * ROWB)      // 79872
#define B_HI  (A1_LO + M_TILE * ROWB)      // 106496
#define B_LO  (B_HI + 256 * ROWB)          // 159744
#define WOUT  (B_LO + 256 * ROWB)          // 212992
#define BOUT  (WOUT + O_DIM * H_DIM * 4)   // 215552
#define SMEM_TOTAL (BOUT + 64)             // 215616

__device__ __forceinline__ uint32_t smem_u32(const void* p) {
    uint32_t a;
    asm("{ .reg .u64 t; cvta.to.shared.u64 t, %1; cvt.u32.u64 %0, t; }" : "=r"(a) : "l"(p));
    return a;
}

#define LDSM_X4(r, addr)                                                     \
    asm volatile("ldmatrix.sync.aligned.m8n8.x4.shared.b16 {%0,%1,%2,%3}, [%4];" \
                 : "=r"((r)[0]), "=r"((r)[1]), "=r"((r)[2]), "=r"((r)[3])    \
                 : "r"(addr))

#define MMA16816(d, a, b0v, b1v)                                             \
    asm volatile("mma.sync.aligned.m16n8k16.row.col.f32.bf16.bf16.f32 "      \
                 "{%0,%1,%2,%3},{%4,%5,%6,%7},{%8,%9},{%0,%1,%2,%3};"        \
                 : "+f"((d)[0]), "+f"((d)[1]), "+f"((d)[2]), "+f"((d)[3])    \
                 : "r"((a)[0]), "r"((a)[1]), "r"((a)[2]), "r"((a)[3]),       \
                   "r"(b0v), "r"(b1v))

__device__ __forceinline__ float sigf(float x) {
    return __fdividef(1.0f, 1.0f + __expf(-x));
}
__device__ __forceinline__ uint32_t pack_bf16x2(float a, float b) {
    __nv_bfloat16 ha = __float2bfloat16(a), hb = __float2bfloat16(b);
    return (uint32_t)__bfloat16_as_ushort(ha) | ((uint32_t)__bfloat16_as_ushort(hb) << 16);
}

__global__ __launch_bounds__(NTHREADS, 1)
void lstm_mma_kernel(const float* __restrict__ x,
                     const float* __restrict__ W_ih,
                     const float* __restrict__ W_hh,
                     const float* __restrict__ b_ih,
                     const float* __restrict__ b_hh,
                     const float* __restrict__ W_out,
                     const float* __restrict__ b_out,
                     float* __restrict__ out)
{
    extern __shared__ char smc[];
    const uint32_t sb = smem_u32(smc);
    const int tid  = threadIdx.x;
    const int wid  = tid >> 5;
    const int lane = tid & 31;
    const int b0   = blockIdx.x * M_TILE;

    float* Wout_s = (float*)(smc + WOUT);
    float* bout_s = (float*)(smc + BOUT);

    // ---- zero A/B tiles, then stage ----
    for (int i = tid; i < (B_LO + 256 * ROWB) / 4; i += NTHREADS)
        ((uint32_t*)smc)[i] = 0u;
    __syncthreads();

    // B = [W_hh | W_ih | bias] hi/lo splits, row n, K-major
    for (int idx = tid; idx < 256 * H_DIM; idx += NTHREADS) {
        int n = idx >> 6, k = idx & 63;
        float v = W_hh[idx];
        __nv_bfloat16 h = __float2bfloat16(v);
        *(__nv_bfloat16*)(smc + B_HI + n * ROWB + k * 2) = h;
        *(__nv_bfloat16*)(smc + B_LO + n * ROWB + k * 2) =
            __float2bfloat16(v - __bfloat162float(h));
    }
    for (int idx = tid; idx < 256 * I_DIM; idx += NTHREADS) {
        int n = idx / I_DIM, i = idx % I_DIM;
        float v = W_ih[idx];
        __nv_bfloat16 h = __float2bfloat16(v);
        *(__nv_bfloat16*)(smc + B_HI + n * ROWB + (64 + i) * 2) = h;
        *(__nv_bfloat16*)(smc + B_LO + n * ROWB + (64 + i) * 2) =
            __float2bfloat16(v - __bfloat162float(h));
    }
    for (int n = tid; n < 256; n += NTHREADS) {
        float v = b_ih[n] + b_hh[n];
        __nv_bfloat16 h = __float2bfloat16(v);
        *(__nv_bfloat16*)(smc + B_HI + n * ROWB + 92 * 2) = h;
        *(__nv_bfloat16*)(smc + B_LO + n * ROWB + 92 * 2) =
            __float2bfloat16(v - __bfloat162float(h));
    }
    // constant-1 column k=92 in both A_hi buffers (lo stays 0)
    if (tid < M_TILE) {
        *(__nv_bfloat16*)(smc + A0_HI + tid * ROWB + 92 * 2) = __float2bfloat16(1.0f);
        *(__nv_bfloat16*)(smc + A1_HI + tid * ROWB + 92 * 2) = __float2bfloat16(1.0f);
    }
    for (int i = tid; i < O_DIM * H_DIM; i += NTHREADS) Wout_s[i] = W_out[i];
    if (tid < O_DIM) bout_s[tid] = b_out[tid];
    __syncthreads();

    // warp tiling: wm (0..3) -> rows [32wm, 32wm+32); wn (0..1) -> units [32wn, 32wn+32)
    const int wm = wid & 3;
    const int wn = wid >> 2;
    const int lg = lane >> 3, lr = lane & 7;     // ldmatrix group / row-in-group

    // A (non-trans): m0 rows0-7@k0, m1 rows8-15@k0, m2 rows0-7@k8, m3 rows8-15@k8
    const int a_row_off = ((lg & 1) * 8 + lr);
    const int a_k_off   = (lg >> 1) * 8;
    // B (non-trans, [n][k] smem): m0 n0-7@k0, m1 n0-7@k8, m2 n8-15@k0, m3 n8-15@k8
    // fragment u2: b0 = r[2*u2] (k0-7), b1 = r[2*u2+1] (k8-15)
    const int b_n_off   = ((lg >> 1) * 8 + lr);
    const int b_k_off   = (lg & 1) * 8;

    // c state
    float cs[32];
#pragma unroll
    for (int i = 0; i < 32; ++i) cs[i] = 0.0f;

    // x staging: thread -> (row, half of 28 inputs)
    const int xrow  = tid >> 1;
    const int xhalf = tid & 1;
    const float* xbase = x + (size_t)(b0 + xrow) * (T_STEPS * I_DIM) + xhalf * 14;

    const int ep_row_base = wm * 32 + (lane >> 2);      // + mt*16 + rh*8
    const int ep_col_base = wn * 32 + 2 * (lane & 3);   // + uj*8

    for (int t = 0; t < T_STEPS; ++t) {
        const uint32_t curHI = sb + ((t & 1) ? A1_HI : A0_HI);
        const uint32_t curLO = sb + ((t & 1) ? A1_LO : A0_LO);
        const uint32_t nxtHI = sb + ((t & 1) ? A0_HI : A1_HI);
        const uint32_t nxtLO = sb + ((t & 1) ? A0_LO : A1_LO);

        // ---- stage x_t (hi/lo) into current A buffer, cols 64..91 ----
        {
            const float2* xp = (const float2*)(xbase + t * I_DIM);
            const uint32_t rbase = (uint32_t)xrow * ROWB + (64 + xhalf * 14) * 2;
#pragma unroll
            for (int j = 0; j < 7; ++j) {
                float2 v = xp[j];
                __nv_bfloat16 h0 = __float2bfloat16(v.x), h1 = __float2bfloat16(v.y);
                *(uint32_t*)(smc + (curHI - sb) + rbase + 4 * j) =
                    (uint32_t)__bfloat16_as_ushort(h0) | ((uint32_t)__bfloat16_as_ushort(h1) << 16);
                *(uint32_t*)(smc + (curLO - sb) + rbase + 4 * j) =
                    pack_bf16x2(v.x - __bfloat162float(h0), v.y - __bfloat162float(h1));
            }
        }
        __syncthreads();   // h (prev epilogue) + x visible to all warps

        // ---- two n-half phases: MMA (3-pass split) then thread-local epilogue ----
#pragma unroll
        for (int uh = 0; uh < 2; ++uh) {
            float acc[2][2][4][4];   // [mt][u2][gate][frag]
#pragma unroll
            for (int mt = 0; mt < 2; ++mt)
#pragma unroll
                for (int u2 = 0; u2 < 2; ++u2)
#pragma unroll
                    for (int g = 0; g < 4; ++g)
#pragma unroll
                        for (int r = 0; r < 4; ++r) acc[mt][u2][g][r] = 0.0f;

#pragma unroll
            for (int ks = 0; ks < 6; ++ks) {
                const int k0 = ks * 16;
                uint32_t ah[2][4], al[2][4];
#pragma unroll
                for (int mt = 0; mt < 2; ++mt) {
                    uint32_t off = (uint32_t)(wm * 32 + mt * 16 + a_row_off) * ROWB
                                 + (uint32_t)(k0 + a_k_off) * 2;
                    LDSM_X4(ah[mt], curHI + off);
                    LDSM_X4(al[mt], curLO + off);
                }
                uint32_t bh[4][4], bl[4][4];
#pragma unroll
                for (int g = 0; g < 4; ++g) {
                    uint32_t off = (uint32_t)(g * 64 + wn * 32 + uh * 16 + b_n_off) * ROWB
                                 + (uint32_t)(k0 + b_k_off) * 2;
                    LDSM_X4(bh[g], sb + B_HI + off);
                    LDSM_X4(bl[g], sb + B_LO + off);
                }
#pragma unroll
                for (int mt = 0; mt < 2; ++mt)
#pragma unroll
                    for (int u2 = 0; u2 < 2; ++u2)
#pragma unroll
                        for (int g = 0; g < 4; ++g) {
                            MMA16816(acc[mt][u2][g], ah[mt], bh[g][u2 * 2], bh[g][u2 * 2 + 1]);
                            MMA16816(acc[mt][u2][g], ah[mt], bl[g][u2 * 2], bl[g][u2 * 2 + 1]);
                            MMA16816(acc[mt][u2][g], al[mt], bh[g][u2 * 2], bh[g][u2 * 2 + 1]);
                        }
            }

            // ---- epilogue for this n-half: gates -> c,h ; h into next buffer ----
#pragma unroll
            for (int mt = 0; mt < 2; ++mt)
#pragma unroll
                for (int rh = 0; rh < 2; ++rh)
#pragma unroll
                    for (int u2 = 0; u2 < 2; ++u2) {
                        const int uj = uh * 2 + u2;
                        float hv[2];
#pragma unroll
                        for (int e = 0; e < 2; ++e) {
                            const int r = rh * 2 + e;
                            float ig = sigf(acc[mt][u2][0][r]);
                            float fg = sigf(acc[mt][u2][1][r]);
                            float gg = 2.0f * sigf(2.0f * acc[mt][u2][2][r]) - 1.0f;
                            float og = sigf(acc[mt][u2][3][r]);
                            const int ci = ((mt * 2 + rh) * 4 + uj) * 2 + e;
                            float cn = fg * cs[ci] + ig * gg;
                            cs[ci] = cn;
                            hv[e] = og * (2.0f * sigf(2.0f * cn) - 1.0f);
                        }
                        __nv_bfloat16 h0 = __float2bfloat16(hv[0]);
                        __nv_bfloat16 h1 = __float2bfloat16(hv[1]);
                        const uint32_t off =
                            (uint32_t)(ep_row_base + mt * 16 + rh * 8) * ROWB
                          + (uint32_t)(ep_col_base + uj * 8) * 2;
                        *(uint32_t*)(smc + (nxtHI - sb) + off) =
                            (uint32_t)__bfloat16_as_ushort(h0) |
                            ((uint32_t)__bfloat16_as_ushort(h1) << 16);
                        *(uint32_t*)(smc + (nxtLO - sb) + off) =
                            pack_bf16x2(hv[0] - __bfloat162float(h0),
                                        hv[1] - __bfloat162float(h1));
                    }
        }
    }
    __syncthreads();   // final h (in buffer 0, since T even) visible

    // ---- output projection ----
    float* part = (float*)(smc + B_LO);   // reuse: [2][128][10]
    {
        const int uh2 = tid >> 7, r2 = tid & 127;
        float acc[O_DIM];
#pragma unroll
        for (int o = 0; o < O_DIM; ++o) acc[o] = 0.0f;
#pragma unroll
        for (int j = 0; j < 32; ++j) {
            const int u = uh2 * 32 + j;
            float hv = __bfloat162float(*(__nv_bfloat16*)(smc + A0_HI + r2 * ROWB + u * 2))
                     + __bfloat162float(*(__nv_bfloat16*)(smc + A0_LO + r2 * ROWB + u * 2));
#pragma unroll
            for (int o = 0; o < O_DIM; ++o)
                acc[o] = fmaf(hv, Wout_s[o * H_DIM + u], acc[o]);
        }
        __syncthreads();
#pragma unroll
        for (int o = 0; o < O_DIM; ++o)
            part[(uh2 * M_TILE + r2) * O_DIM + o] = acc[o];
    }
    __syncthreads();
    for (int idx = tid; idx < M_TILE * O_DIM; idx += NTHREADS) {
        int r = idx / O_DIM, o = idx % O_DIM;
        out[(size_t)(b0 + r) * O_DIM + o] =
            part[r * O_DIM + o] + part[(M_TILE + r) * O_DIM + o] + bout_s[o];
    }
}

extern "C" void kernel_launch(void* const* d_in, const int* in_sizes, int n_in,
                              void* d_out, int out_size)
{
    const float* x     = (const float*)d_in[0];
    const float* W_ih  = (const float*)d_in[1];
    const float* W_hh  = (const float*)d_in[2];
    const float* b_ih  = (const float*)d_in[3];
    const float* b_hh  = (const float*)d_in[4];
    const float* W_out = (const float*)d_in[5];
    const float* b_out = (const float*)d_in[6];
    float* out = (float*)d_out;

    cudaFuncSetAttribute(lstm_mma_kernel,
                         cudaFuncAttributeMaxDynamicSharedMemorySize, SMEM_TOTAL);

    lstm_mma_kernel<<<B_TOTAL / M_TILE, NTHREADS, SMEM_TOTAL>>>(
        x, W_ih, W_hh, b_ih, b_hh, W_out, b_out, out);
}

// round 8
// speedup vs baseline: 3.6435x; 1.2094x over previous
#include <cuda_runtime.h>
#include <cuda_bf16.h>
#include <cstdint>

// LSTM via mma.sync (HMMA). B=65536, T=28, I=28, H=64, O=10.
// R8: tanh.approx.f32 epilogue (5 MUFU/elem instead of 10 MUFU+extras) and
// software-pipelined x prefetch (LDG for t+1 issued under timestep-t compute).
// Structure otherwise = R7: per CTA 128 rows, D[128,256]=A[128,96]@W[256,96]^T,
// 3-pass bf16 split (Ah@Bh + Ah@Bl + Al@Bh), h double-buffered, 1 barrier/t.

#define T_STEPS  28
#define I_DIM    28
#define H_DIM    64
#define O_DIM    10
#define M_TILE   128
#define NTHREADS 256
#define B_TOTAL  65536

#define KSTRIDE  104                  // bf16 elems per row (208 B, LDSM conflict-free)
#define ROWB     (KSTRIDE * 2)        // 208 bytes

// smem byte offsets
#define A0_HI 0
#define A0_LO (A0_HI + M_TILE * ROWB)      // 26624
#define A1_HI (A0_LO + M_TILE * ROWB)      // 53248
#define A1_LO (A1_HI + M_TILE * ROWB)      // 79872
#define B_HI  (A1_LO + M_TILE * ROWB)      // 106496
#define B_LO  (B_HI + 256 * ROWB)          // 159744
#define WOUT  (B_LO + 256 * ROWB)          // 212992
#define BOUT  (WOUT + O_DIM * H_DIM * 4)   // 215552
#define SMEM_TOTAL (BOUT + 64)             // 215616

__device__ __forceinline__ uint32_t smem_u32(const void* p) {
    uint32_t a;
    asm("{ .reg .u64 t; cvta.to.shared.u64 t, %1; cvt.u32.u64 %0, t; }" : "=r"(a) : "l"(p));
    return a;
}

#define LDSM_X4(r, addr)                                                     \
    asm volatile("ldmatrix.sync.aligned.m8n8.x4.shared.b16 {%0,%1,%2,%3}, [%4];" \
                 : "=r"((r)[0]), "=r"((r)[1]), "=r"((r)[2]), "=r"((r)[3])    \
                 : "r"(addr))

#define MMA16816(d, a, b0v, b1v)                                             \
    asm volatile("mma.sync.aligned.m16n8k16.row.col.f32.bf16.bf16.f32 "      \
                 "{%0,%1,%2,%3},{%4,%5,%6,%7},{%8,%9},{%0,%1,%2,%3};"        \
                 : "+f"((d)[0]), "+f"((d)[1]), "+f"((d)[2]), "+f"((d)[3])    \
                 : "r"((a)[0]), "r"((a)[1]), "r"((a)[2]), "r"((a)[3]),       \
                   "r"(b0v), "r"(b1v))

__device__ __forceinline__ float tanha(float x) {
    float r; asm("tanh.approx.f32 %0, %1;" : "=f"(r) : "f"(x)); return r;
}
__device__ __forceinline__ float siga(float x) {          // sigmoid via tanh
    return fmaf(tanha(0.5f * x), 0.5f, 0.5f);
}
__device__ __forceinline__ uint32_t pack_bf16x2(float a, float b) {
    __nv_bfloat16 ha = __float2bfloat16(a), hb = __float2bfloat16(b);
    return (uint32_t)__bfloat16_as_ushort(ha) | ((uint32_t)__bfloat16_as_ushort(hb) << 16);
}

__global__ __launch_bounds__(NTHREADS, 1)
void lstm_mma_kernel(const float* __restrict__ x,
                     const float* __restrict__ W_ih,
                     const float* __restrict__ W_hh,
                     const float* __restrict__ b_ih,
                     const float* __restrict__ b_hh,
                     const float* __restrict__ W_out,
                     const float* __restrict__ b_out,
                     float* __restrict__ out)
{
    extern __shared__ char smc[];
    const uint32_t sb = smem_u32(smc);
    const int tid  = threadIdx.x;
    const int wid  = tid >> 5;
    const int lane = tid & 31;
    const int b0   = blockIdx.x * M_TILE;

    float* Wout_s = (float*)(smc + WOUT);
    float* bout_s = (float*)(smc + BOUT);

    // ---- zero A/B tiles, then stage ----
    for (int i = tid; i < (B_LO + 256 * ROWB) / 4; i += NTHREADS)
        ((uint32_t*)smc)[i] = 0u;
    __syncthreads();

    // B = [W_hh | W_ih | bias] hi/lo splits, row n, K-major
    for (int idx = tid; idx < 256 * H_DIM; idx += NTHREADS) {
        int n = idx >> 6, k = idx & 63;
        float v = W_hh[idx];
        __nv_bfloat16 h = __float2bfloat16(v);
        *(__nv_bfloat16*)(smc + B_HI + n * ROWB + k * 2) = h;
        *(__nv_bfloat16*)(smc + B_LO + n * ROWB + k * 2) =
            __float2bfloat16(v - __bfloat162float(h));
    }
    for (int idx = tid; idx < 256 * I_DIM; idx += NTHREADS) {
        int n = idx / I_DIM, i = idx % I_DIM;
        float v = W_ih[idx];
        __nv_bfloat16 h = __float2bfloat16(v);
        *(__nv_bfloat16*)(smc + B_HI + n * ROWB + (64 + i) * 2) = h;
        *(__nv_bfloat16*)(smc + B_LO + n * ROWB + (64 + i) * 2) =
            __float2bfloat16(v - __bfloat162float(h));
    }
    for (int n = tid; n < 256; n += NTHREADS) {
        float v = b_ih[n] + b_hh[n];
        __nv_bfloat16 h = __float2bfloat16(v);
        *(__nv_bfloat16*)(smc + B_HI + n * ROWB + 92 * 2) = h;
        *(__nv_bfloat16*)(smc + B_LO + n * ROWB + 92 * 2) =
            __float2bfloat16(v - __bfloat162float(h));
    }
    // constant-1 column k=92 in both A_hi buffers (lo stays 0)
    if (tid < M_TILE) {
        *(__nv_bfloat16*)(smc + A0_HI + tid * ROWB + 92 * 2) = __float2bfloat16(1.0f);
        *(__nv_bfloat16*)(smc + A1_HI + tid * ROWB + 92 * 2) = __float2bfloat16(1.0f);
    }
    for (int i = tid; i < O_DIM * H_DIM; i += NTHREADS) Wout_s[i] = W_out[i];
    if (tid < O_DIM) bout_s[tid] = b_out[tid];
    __syncthreads();

    // warp tiling: wm (0..3) -> rows [32wm, 32wm+32); wn (0..1) -> units [32wn, 32wn+32)
    const int wm = wid & 3;
    const int wn = wid >> 2;
    const int lg = lane >> 3, lr = lane & 7;

    // A (non-trans): m0 rows0-7@k0, m1 rows8-15@k0, m2 rows0-7@k8, m3 rows8-15@k8
    const int a_row_off = ((lg & 1) * 8 + lr);
    const int a_k_off   = (lg >> 1) * 8;
    // B (non-trans, [n][k]): m0 n0-7@k0, m1 n0-7@k8, m2 n8-15@k0, m3 n8-15@k8
    const int b_n_off   = ((lg >> 1) * 8 + lr);
    const int b_k_off   = (lg & 1) * 8;

    float cs[32];
#pragma unroll
    for (int i = 0; i < 32; ++i) cs[i] = 0.0f;

    // x prefetch: thread -> (row, half of 28 inputs)
    const int xrow  = tid >> 1;
    const int xhalf = tid & 1;
    const float* xbase = x + (size_t)(b0 + xrow) * (T_STEPS * I_DIM) + xhalf * 14;

    const int ep_row_base = wm * 32 + (lane >> 2);      // + mt*16 + rh*8
    const int ep_col_base = wn * 32 + 2 * (lane & 3);   // + uj*8

    // prefetch x(0)
    float2 xpre[7];
    {
        const float2* xp = (const float2*)xbase;
#pragma unroll
        for (int j = 0; j < 7; ++j) xpre[j] = xp[j];
    }

    for (int t = 0; t < T_STEPS; ++t) {
        const uint32_t curHI = sb + ((t & 1) ? A1_HI : A0_HI);
        const uint32_t curLO = sb + ((t & 1) ? A1_LO : A0_LO);
        const uint32_t nxtHI = sb + ((t & 1) ? A0_HI : A1_HI);
        const uint32_t nxtLO = sb + ((t & 1) ? A0_LO : A1_LO);

        // ---- store prefetched x_t (hi/lo) into current A buffer, cols 64..91 ----
        {
            const uint32_t rbase = (uint32_t)xrow * ROWB + (64 + xhalf * 14) * 2;
#pragma unroll
            for (int j = 0; j < 7; ++j) {
                float2 v = xpre[j];
                __nv_bfloat16 h0 = __float2bfloat16(v.x), h1 = __float2bfloat16(v.y);
                *(uint32_t*)(smc + (curHI - sb) + rbase + 4 * j) =
                    (uint32_t)__bfloat16_as_ushort(h0) | ((uint32_t)__bfloat16_as_ushort(h1) << 16);
                *(uint32_t*)(smc + (curLO - sb) + rbase + 4 * j) =
                    pack_bf16x2(v.x - __bfloat162float(h0), v.y - __bfloat162float(h1));
            }
        }
        // ---- prefetch x(t+1): LDG latency hides under MMA + epilogue ----
        if (t + 1 < T_STEPS) {
            const float2* xp = (const float2*)(xbase + (t + 1) * I_DIM);
#pragma unroll
            for (int j = 0; j < 7; ++j) xpre[j] = xp[j];
        }
        __syncthreads();   // h (prev epilogue) + x visible to all warps

        // ---- two n-half phases: MMA (3-pass split) then thread-local epilogue ----
#pragma unroll
        for (int uh = 0; uh < 2; ++uh) {
            float acc[2][2][4][4];   // [mt][u2][gate][frag]
#pragma unroll
            for (int mt = 0; mt < 2; ++mt)
#pragma unroll
                for (int u2 = 0; u2 < 2; ++u2)
#pragma unroll
                    for (int g = 0; g < 4; ++g)
#pragma unroll
                        for (int r = 0; r < 4; ++r) acc[mt][u2][g][r] = 0.0f;

#pragma unroll
            for (int ks = 0; ks < 6; ++ks) {
                const int k0 = ks * 16;
                uint32_t ah[2][4], al[2][4];
#pragma unroll
                for (int mt = 0; mt < 2; ++mt) {
                    uint32_t off = (uint32_t)(wm * 32 + mt * 16 + a_row_off) * ROWB
                                 + (uint32_t)(k0 + a_k_off) * 2;
                    LDSM_X4(ah[mt], curHI + off);
                    LDSM_X4(al[mt], curLO + off);
                }
                uint32_t bh[4][4], bl[4][4];
#pragma unroll
                for (int g = 0; g < 4; ++g) {
                    uint32_t off = (uint32_t)(g * 64 + wn * 32 + uh * 16 + b_n_off) * ROWB
                                 + (uint32_t)(k0 + b_k_off) * 2;
                    LDSM_X4(bh[g], sb + B_HI + off);
                    LDSM_X4(bl[g], sb + B_LO + off);
                }
#pragma unroll
                for (int mt = 0; mt < 2; ++mt)
#pragma unroll
                    for (int u2 = 0; u2 < 2; ++u2)
#pragma unroll
                        for (int g = 0; g < 4; ++g) {
                            MMA16816(acc[mt][u2][g], ah[mt], bh[g][u2 * 2], bh[g][u2 * 2 + 1]);
                            MMA16816(acc[mt][u2][g], ah[mt], bl[g][u2 * 2], bl[g][u2 * 2 + 1]);
                            MMA16816(acc[mt][u2][g], al[mt], bh[g][u2 * 2], bh[g][u2 * 2 + 1]);
                        }
            }

            // ---- epilogue for this n-half (tanh.approx activations) ----
#pragma unroll
            for (int mt = 0; mt < 2; ++mt)
#pragma unroll
                for (int rh = 0; rh < 2; ++rh)
#pragma unroll
                    for (int u2 = 0; u2 < 2; ++u2) {
                        const int uj = uh * 2 + u2;
                        float hv[2];
#pragma unroll
                        for (int e = 0; e < 2; ++e) {
                            const int r = rh * 2 + e;
                            float ig = siga(acc[mt][u2][0][r]);
                            float fg = siga(acc[mt][u2][1][r]);
                            float gg = tanha(acc[mt][u2][2][r]);
                            float og = siga(acc[mt][u2][3][r]);
                            const int ci = ((mt * 2 + rh) * 4 + uj) * 2 + e;
                            float cn = fg * cs[ci] + ig * gg;
                            cs[ci] = cn;
                            hv[e] = og * tanha(cn);
                        }
                        __nv_bfloat16 h0 = __float2bfloat16(hv[0]);
                        __nv_bfloat16 h1 = __float2bfloat16(hv[1]);
                        const uint32_t off =
                            (uint32_t)(ep_row_base + mt * 16 + rh * 8) * ROWB
                          + (uint32_t)(ep_col_base + uj * 8) * 2;
                        *(uint32_t*)(smc + (nxtHI - sb) + off) =
                            (uint32_t)__bfloat16_as_ushort(h0) |
                            ((uint32_t)__bfloat16_as_ushort(h1) << 16);
                        *(uint32_t*)(smc + (nxtLO - sb) + off) =
                            pack_bf16x2(hv[0] - __bfloat162float(h0),
                                        hv[1] - __bfloat162float(h1));
                    }
        }
    }
    __syncthreads();   // final h (in buffer 0, since T even) visible

    // ---- output projection ----
    float* part = (float*)(smc + B_LO);   // reuse: [2][128][10]
    {
        const int uh2 = tid >> 7, r2 = tid & 127;
        float acc[O_DIM];
#pragma unroll
        for (int o = 0; o < O_DIM; ++o) acc[o] = 0.0f;
#pragma unroll
        for (int j = 0; j < 32; ++j) {
            const int u = uh2 * 32 + j;
            float hv = __bfloat162float(*(__nv_bfloat16*)(smc + A0_HI + r2 * ROWB + u * 2))
                     + __bfloat162float(*(__nv_bfloat16*)(smc + A0_LO + r2 * ROWB + u * 2));
#pragma unroll
            for (int o = 0; o < O_DIM; ++o)
                acc[o] = fmaf(hv, Wout_s[o * H_DIM + u], acc[o]);
        }
        __syncthreads();
#pragma unroll
        for (int o = 0; o < O_DIM; ++o)
            part[(uh2 * M_TILE + r2) * O_DIM + o] = acc[o];
    }
    __syncthreads();
    for (int idx = tid; idx < M_TILE * O_DIM; idx += NTHREADS) {
        int r = idx / O_DIM, o = idx % O_DIM;
        out[(size_t)(b0 + r) * O_DIM + o] =
            part[r * O_DIM + o] + part[(M_TILE + r) * O_DIM + o] + bout_s[o];
    }
}

extern "C" void kernel_launch(void* const* d_in, const int* in_sizes, int n_in,
                              void* d_out, int out_size)
{
    const float* x     = (const float*)d_in[0];
    const float* W_ih  = (const float*)d_in[1];
    const float* W_hh  = (const float*)d_in[2];
    const float* b_ih  = (const float*)d_in[3];
    const float* b_hh  = (const float*)d_in[4];
    const float* W_out = (const float*)d_in[5];
    const float* b_out = (const float*)d_in[6];
    float* out = (float*)d_out;

    cudaFuncSetAttribute(lstm_mma_kernel,
                         cudaFuncAttributeMaxDynamicSharedMemorySize, SMEM_TOTAL);

    lstm_mma_kernel<<<B_TOTAL / M_TILE, NTHREADS, SMEM_TOTAL>>>(
        x, W_ih, W_hh, b_ih, b_hh, W_out, b_out, out);
}

// round 9
// speedup vs baseline: 4.0105x; 1.1007x over previous
#include <cuda_runtime.h>
#include <cuda_bf16.h>
#include <cstdint>

// LSTM via mma.sync (HMMA). B=65536, T=28, I=28, H=64, O=10.
// R9: 512 threads (16 warps, 8m x 2n grid); per-warp tile 16 rows x 32 units.
// Same smem/CTA shape as R8; goal is de-phasing tensor/MUFU/LSU bursts.

#define T_STEPS  28
#define I_DIM    28
#define H_DIM    64
#define O_DIM    10
#define M_TILE   128
#define NTHREADS 512
#define B_TOTAL  65536

#define KSTRIDE  104                  // bf16 elems per row (208 B, LDSM conflict-free)
#define ROWB     (KSTRIDE * 2)        // 208 bytes

// smem byte offsets
#define A0_HI 0
#define A0_LO (A0_HI + M_TILE * ROWB)      // 26624
#define A1_HI (A0_LO + M_TILE * ROWB)      // 53248
#define A1_LO (A1_HI + M_TILE * ROWB)      // 79872
#define B_HI  (A1_LO + M_TILE * ROWB)      // 106496
#define B_LO  (B_HI + 256 * ROWB)          // 159744
#define WOUT  (B_LO + 256 * ROWB)          // 212992
#define BOUT  (WOUT + O_DIM * H_DIM * 4)   // 215552
#define SMEM_TOTAL (BOUT + 64)             // 215616

__device__ __forceinline__ uint32_t smem_u32(const void* p) {
    uint32_t a;
    asm("{ .reg .u64 t; cvta.to.shared.u64 t, %1; cvt.u32.u64 %0, t; }" : "=r"(a) : "l"(p));
    return a;
}

#define LDSM_X4(r, addr)                                                     \
    asm volatile("ldmatrix.sync.aligned.m8n8.x4.shared.b16 {%0,%1,%2,%3}, [%4];" \
                 : "=r"((r)[0]), "=r"((r)[1]), "=r"((r)[2]), "=r"((r)[3])    \
                 : "r"(addr))

#define MMA16816(d, a, b0v, b1v)                                             \
    asm volatile("mma.sync.aligned.m16n8k16.row.col.f32.bf16.bf16.f32 "      \
                 "{%0,%1,%2,%3},{%4,%5,%6,%7},{%8,%9},{%0,%1,%2,%3};"        \
                 : "+f"((d)[0]), "+f"((d)[1]), "+f"((d)[2]), "+f"((d)[3])    \
                 : "r"((a)[0]), "r"((a)[1]), "r"((a)[2]), "r"((a)[3]),       \
                   "r"(b0v), "r"(b1v))

__device__ __forceinline__ float tanha(float x) {
    float r; asm("tanh.approx.f32 %0, %1;" : "=f"(r) : "f"(x)); return r;
}
__device__ __forceinline__ float siga(float x) {
    return fmaf(tanha(0.5f * x), 0.5f, 0.5f);
}
__device__ __forceinline__ uint32_t pack_bf16x2(float a, float b) {
    __nv_bfloat16 ha = __float2bfloat16(a), hb = __float2bfloat16(b);
    return (uint32_t)__bfloat16_as_ushort(ha) | ((uint32_t)__bfloat16_as_ushort(hb) << 16);
}

__global__ __launch_bounds__(NTHREADS, 1)
void lstm_mma_kernel(const float* __restrict__ x,
                     const float* __restrict__ W_ih,
                     const float* __restrict__ W_hh,
                     const float* __restrict__ b_ih,
                     const float* __restrict__ b_hh,
                     const float* __restrict__ W_out,
                     const float* __restrict__ b_out,
                     float* __restrict__ out)
{
    extern __shared__ char smc[];
    const uint32_t sb = smem_u32(smc);
    const int tid  = threadIdx.x;
    const int wid  = tid >> 5;
    const int lane = tid & 31;
    const int b0   = blockIdx.x * M_TILE;

    float* Wout_s = (float*)(smc + WOUT);
    float* bout_s = (float*)(smc + BOUT);

    // ---- zero A/B tiles, then stage ----
    for (int i = tid; i < (B_LO + 256 * ROWB) / 4; i += NTHREADS)
        ((uint32_t*)smc)[i] = 0u;
    __syncthreads();

    // B = [W_hh | W_ih | bias] hi/lo splits, row n, K-major
    for (int idx = tid; idx < 256 * H_DIM; idx += NTHREADS) {
        int n = idx >> 6, k = idx & 63;
        float v = W_hh[idx];
        __nv_bfloat16 h = __float2bfloat16(v);
        *(__nv_bfloat16*)(smc + B_HI + n * ROWB + k * 2) = h;
        *(__nv_bfloat16*)(smc + B_LO + n * ROWB + k * 2) =
            __float2bfloat16(v - __bfloat162float(h));
    }
    for (int idx = tid; idx < 256 * I_DIM; idx += NTHREADS) {
        int n = idx / I_DIM, i = idx % I_DIM;
        float v = W_ih[idx];
        __nv_bfloat16 h = __float2bfloat16(v);
        *(__nv_bfloat16*)(smc + B_HI + n * ROWB + (64 + i) * 2) = h;
        *(__nv_bfloat16*)(smc + B_LO + n * ROWB + (64 + i) * 2) =
            __float2bfloat16(v - __bfloat162float(h));
    }
    for (int n = tid; n < 256; n += NTHREADS) {
        float v = b_ih[n] + b_hh[n];
        __nv_bfloat16 h = __float2bfloat16(v);
        *(__nv_bfloat16*)(smc + B_HI + n * ROWB + 92 * 2) = h;
        *(__nv_bfloat16*)(smc + B_LO + n * ROWB + 92 * 2) =
            __float2bfloat16(v - __bfloat162float(h));
    }
    if (tid < M_TILE) {
        *(__nv_bfloat16*)(smc + A0_HI + tid * ROWB + 92 * 2) = __float2bfloat16(1.0f);
        *(__nv_bfloat16*)(smc + A1_HI + tid * ROWB + 92 * 2) = __float2bfloat16(1.0f);
    }
    for (int i = tid; i < O_DIM * H_DIM; i += NTHREADS) Wout_s[i] = W_out[i];
    if (tid < O_DIM) bout_s[tid] = b_out[tid];
    __syncthreads();

    // warp tiling: wm (0..7) -> rows [16wm, 16wm+16); wn (0..1) -> units [32wn, 32wn+32)
    const int wm = wid & 7;
    const int wn = wid >> 3;
    const int lg = lane >> 3, lr = lane & 7;

    // A (non-trans): m0 rows0-7@k0, m1 rows8-15@k0, m2 rows0-7@k8, m3 rows8-15@k8
    const int a_row_off = ((lg & 1) * 8 + lr);
    const int a_k_off   = (lg >> 1) * 8;
    // B (non-trans, [n][k]): m0 n0-7@k0, m1 n0-7@k8, m2 n8-15@k0, m3 n8-15@k8
    const int b_n_off   = ((lg >> 1) * 8 + lr);
    const int b_k_off   = (lg & 1) * 8;

    // c state: cs[(rh*4 + uj)*2 + e], rh 0..1 (row +8), uj 0..3 (unit group), e 0..1
    float cs[16];
#pragma unroll
    for (int i = 0; i < 16; ++i) cs[i] = 0.0f;

    // x prefetch: threads 0..255 -> (row = tid>>1, half = tid&1)
    const int xrow  = (tid & 255) >> 1;
    const int xhalf = tid & 1;
    const bool xactive = (tid < 256);
    const float* xbase = x + (size_t)(b0 + xrow) * (T_STEPS * I_DIM) + xhalf * 14;

    const int ep_row_base = wm * 16 + (lane >> 2);      // + rh*8
    const int ep_col_base = wn * 32 + 2 * (lane & 3);   // + uj*8

    float2 xpre[7];
    if (xactive) {
        const float2* xp = (const float2*)xbase;
#pragma unroll
        for (int j = 0; j < 7; ++j) xpre[j] = xp[j];
    }

    for (int t = 0; t < T_STEPS; ++t) {
        const uint32_t curHI = sb + ((t & 1) ? A1_HI : A0_HI);
        const uint32_t curLO = sb + ((t & 1) ? A1_LO : A0_LO);
        const uint32_t nxtHI = sb + ((t & 1) ? A0_HI : A1_HI);
        const uint32_t nxtLO = sb + ((t & 1) ? A0_LO : A1_LO);

        if (xactive) {
            const uint32_t rbase = (uint32_t)xrow * ROWB + (64 + xhalf * 14) * 2;
#pragma unroll
            for (int j = 0; j < 7; ++j) {
                float2 v = xpre[j];
                __nv_bfloat16 h0 = __float2bfloat16(v.x), h1 = __float2bfloat16(v.y);
                *(uint32_t*)(smc + (curHI - sb) + rbase + 4 * j) =
                    (uint32_t)__bfloat16_as_ushort(h0) | ((uint32_t)__bfloat16_as_ushort(h1) << 16);
                *(uint32_t*)(smc + (curLO - sb) + rbase + 4 * j) =
                    pack_bf16x2(v.x - __bfloat162float(h0), v.y - __bfloat162float(h1));
            }
            if (t + 1 < T_STEPS) {
                const float2* xp = (const float2*)(xbase + (t + 1) * I_DIM);
#pragma unroll
                for (int j = 0; j < 7; ++j) xpre[j] = xp[j];
            }
        }
        __syncthreads();   // h (prev epilogue) + x visible

        // ---- two n-half phases ----
#pragma unroll
        for (int uh = 0; uh < 2; ++uh) {
            float acc[2][4][4];   // [u2][gate][frag]
#pragma unroll
            for (int u2 = 0; u2 < 2; ++u2)
#pragma unroll
                for (int g = 0; g < 4; ++g)
#pragma unroll
                    for (int r = 0; r < 4; ++r) acc[u2][g][r] = 0.0f;

#pragma unroll
            for (int ks = 0; ks < 6; ++ks) {
                const int k0 = ks * 16;
                uint32_t ah[4], al[4];
                {
                    uint32_t off = (uint32_t)(wm * 16 + a_row_off) * ROWB
                                 + (uint32_t)(k0 + a_k_off) * 2;
                    LDSM_X4(ah, curHI + off);
                    LDSM_X4(al, curLO + off);
                }
#pragma unroll
                for (int g = 0; g < 4; ++g) {
                    uint32_t bh[4], bl[4];
                    uint32_t off = (uint32_t)(g * 64 + wn * 32 + uh * 16 + b_n_off) * ROWB
                                 + (uint32_t)(k0 + b_k_off) * 2;
                    LDSM_X4(bh, sb + B_HI + off);
                    LDSM_X4(bl, sb + B_LO + off);
#pragma unroll
                    for (int u2 = 0; u2 < 2; ++u2) {
                        MMA16816(acc[u2][g], ah, bh[u2 * 2], bh[u2 * 2 + 1]);
                        MMA16816(acc[u2][g], ah, bl[u2 * 2], bl[u2 * 2 + 1]);
                        MMA16816(acc[u2][g], al, bh[u2 * 2], bh[u2 * 2 + 1]);
                    }
                }
            }

            // ---- epilogue for this n-half ----
#pragma unroll
            for (int rh = 0; rh < 2; ++rh)
#pragma unroll
                for (int u2 = 0; u2 < 2; ++u2) {
                    const int uj = uh * 2 + u2;
                    float hv[2];
#pragma unroll
                    for (int e = 0; e < 2; ++e) {
                        const int r = rh * 2 + e;
                        float ig = siga(acc[u2][0][r]);
                        float fg = siga(acc[u2][1][r]);
                        float gg = tanha(acc[u2][2][r]);
                        float og = siga(acc[u2][3][r]);
                        const int ci = (rh * 4 + uj) * 2 + e;
                        float cn = fg * cs[ci] + ig * gg;
                        cs[ci] = cn;
                        hv[e] = og * tanha(cn);
                    }
                    __nv_bfloat16 h0 = __float2bfloat16(hv[0]);
                    __nv_bfloat16 h1 = __float2bfloat16(hv[1]);
                    const uint32_t off =
                        (uint32_t)(ep_row_base + rh * 8) * ROWB
                      + (uint32_t)(ep_col_base + uj * 8) * 2;
                    *(uint32_t*)(smc + (nxtHI - sb) + off) =
                        (uint32_t)__bfloat16_as_ushort(h0) |
                        ((uint32_t)__bfloat16_as_ushort(h1) << 16);
                    *(uint32_t*)(smc + (nxtLO - sb) + off) =
                        pack_bf16x2(hv[0] - __bfloat162float(h0),
                                    hv[1] - __bfloat162float(h1));
                }
        }
    }
    __syncthreads();   // final h (buffer 0, T even) visible

    // ---- output projection: 4 partials per row ----
    float* part = (float*)(smc + B_LO);   // [4][128][10] = 20 KB
    {
        const int q = tid >> 7, r2 = tid & 127;   // q 0..3, 16 units each
        float acc[O_DIM];
#pragma unroll
        for (int o = 0; o < O_DIM; ++o) acc[o] = 0.0f;
#pragma unroll
        for (int j = 0; j < 16; ++j) {
            const int u = q * 16 + j;
            float hv = __bfloat162float(*(__nv_bfloat16*)(smc + A0_HI + r2 * ROWB + u * 2))
                     + __bfloat162float(*(__nv_bfloat16*)(smc + A0_LO + r2 * ROWB + u * 2));
#pragma unroll
            for (int o = 0; o < O_DIM; ++o)
                acc[o] = fmaf(hv, Wout_s[o * H_DIM + u], acc[o]);
        }
        __syncthreads();
#pragma unroll
        for (int o = 0; o < O_DIM; ++o)
            part[(q * M_TILE + r2) * O_DIM + o] = acc[o];
    }
    __syncthreads();
    for (int idx = tid; idx < M_TILE * O_DIM; idx += NTHREADS) {
        int r = idx / O_DIM, o = idx % O_DIM;
        out[(size_t)(b0 + r) * O_DIM + o] =
            part[r * O_DIM + o] + part[(M_TILE + r) * O_DIM + o] +
            part[(2 * M_TILE + r) * O_DIM + o] + part[(3 * M_TILE + r) * O_DIM + o] +
            bout_s[o];
    }
}

extern "C" void kernel_launch(void* const* d_in, const int* in_sizes, int n_in,
                              void* d_out, int out_size)
{
    const float* x     = (const float*)d_in[0];
    const float* W_ih  = (const float*)d_in[1];
    const float* W_hh  = (const float*)d_in[2];
    const float* b_ih  = (const float*)d_in[3];
    const float* b_hh  = (const float*)d_in[4];
    const float* W_out = (const float*)d_in[5];
    const float* b_out = (const float*)d_in[6];
    float* out = (float*)d_out;

    cudaFuncSetAttribute(lstm_mma_kernel,
                         cudaFuncAttributeMaxDynamicSharedMemorySize, SMEM_TOTAL);

    lstm_mma_kernel<<<B_TOTAL / M_TILE, NTHREADS, SMEM_TOTAL>>>(
        x, W_ih, W_hh, b_ih, b_hh, W_out, b_out, out);
}

// round 10
// speedup vs baseline: 4.4214x; 1.1025x over previous
#include <cuda_runtime.h>
#include <cuda_bf16.h>
#include <cstdint>

// LSTM via mma.sync (HMMA). B=65536, T=28, I=28, H=64, O=10.
// R10: per-timestep sync is a PAIRWISE named barrier (bar.sync wm+1, 64) between
// the two warps sharing row-range wm, instead of CTA-wide __syncthreads.
// 8 warp-pairs free-run -> epilogue MUFU of one pair overlaps HMMA of others.
// Structure otherwise = R9: 512 thr, 8m x 2n warp grid, 3-pass bf16 split,
// h double-buffered, x prefetch pipelined.

#define T_STEPS  28
#define I_DIM    28
#define H_DIM    64
#define O_DIM    10
#define M_TILE   128
#define NTHREADS 512
#define B_TOTAL  65536

#define KSTRIDE  104
#define ROWB     (KSTRIDE * 2)        // 208 bytes

#define A0_HI 0
#define A0_LO (A0_HI + M_TILE * ROWB)
#define A1_HI (A0_LO + M_TILE * ROWB)
#define A1_LO (A1_HI + M_TILE * ROWB)
#define B_HI  (A1_LO + M_TILE * ROWB)
#define B_LO  (B_HI + 256 * ROWB)
#define WOUT  (B_LO + 256 * ROWB)
#define BOUT  (WOUT + O_DIM * H_DIM * 4)
#define SMEM_TOTAL (BOUT + 64)

__device__ __forceinline__ uint32_t smem_u32(const void* p) {
    uint32_t a;
    asm("{ .reg .u64 t; cvta.to.shared.u64 t, %1; cvt.u32.u64 %0, t; }" : "=r"(a) : "l"(p));
    return a;
}

#define LDSM_X4(r, addr)                                                     \
    asm volatile("ldmatrix.sync.aligned.m8n8.x4.shared.b16 {%0,%1,%2,%3}, [%4];" \
                 : "=r"((r)[0]), "=r"((r)[1]), "=r"((r)[2]), "=r"((r)[3])    \
                 : "r"(addr))

#define MMA16816(d, a, b0v, b1v)                                             \
    asm volatile("mma.sync.aligned.m16n8k16.row.col.f32.bf16.bf16.f32 "      \
                 "{%0,%1,%2,%3},{%4,%5,%6,%7},{%8,%9},{%0,%1,%2,%3};"        \
                 : "+f"((d)[0]), "+f"((d)[1]), "+f"((d)[2]), "+f"((d)[3])    \
                 : "r"((a)[0]), "r"((a)[1]), "r"((a)[2]), "r"((a)[3]),       \
                   "r"(b0v), "r"(b1v))

#define PAIR_BAR(id)                                                          \
    asm volatile("bar.sync %0, 64;" :: "r"((id) + 1) : "memory")

__device__ __forceinline__ float tanha(float x) {
    float r; asm("tanh.approx.f32 %0, %1;" : "=f"(r) : "f"(x)); return r;
}
__device__ __forceinline__ float siga(float x) {
    return fmaf(tanha(0.5f * x), 0.5f, 0.5f);
}
__device__ __forceinline__ uint32_t pack_bf16x2(float a, float b) {
    __nv_bfloat16 ha = __float2bfloat16(a), hb = __float2bfloat16(b);
    return (uint32_t)__bfloat16_as_ushort(ha) | ((uint32_t)__bfloat16_as_ushort(hb) << 16);
}

__global__ __launch_bounds__(NTHREADS, 1)
void lstm_mma_kernel(const float* __restrict__ x,
                     const float* __restrict__ W_ih,
                     const float* __restrict__ W_hh,
                     const float* __restrict__ b_ih,
                     const float* __restrict__ b_hh,
                     const float* __restrict__ W_out,
                     const float* __restrict__ b_out,
                     float* __restrict__ out)
{
    extern __shared__ char smc[];
    const uint32_t sb = smem_u32(smc);
    const int tid  = threadIdx.x;
    const int wid  = tid >> 5;
    const int lane = tid & 31;
    const int b0   = blockIdx.x * M_TILE;

    float* Wout_s = (float*)(smc + WOUT);
    float* bout_s = (float*)(smc + BOUT);

    // ---- zero A/B tiles, then stage ----
    for (int i = tid; i < (B_LO + 256 * ROWB) / 4; i += NTHREADS)
        ((uint32_t*)smc)[i] = 0u;
    __syncthreads();

    for (int idx = tid; idx < 256 * H_DIM; idx += NTHREADS) {
        int n = idx >> 6, k = idx & 63;
        float v = W_hh[idx];
        __nv_bfloat16 h = __float2bfloat16(v);
        *(__nv_bfloat16*)(smc + B_HI + n * ROWB + k * 2) = h;
        *(__nv_bfloat16*)(smc + B_LO + n * ROWB + k * 2) =
            __float2bfloat16(v - __bfloat162float(h));
    }
    for (int idx = tid; idx < 256 * I_DIM; idx += NTHREADS) {
        int n = idx / I_DIM, i = idx % I_DIM;
        float v = W_ih[idx];
        __nv_bfloat16 h = __float2bfloat16(v);
        *(__nv_bfloat16*)(smc + B_HI + n * ROWB + (64 + i) * 2) = h;
        *(__nv_bfloat16*)(smc + B_LO + n * ROWB + (64 + i) * 2) =
            __float2bfloat16(v - __bfloat162float(h));
    }
    for (int n = tid; n < 256; n += NTHREADS) {
        float v = b_ih[n] + b_hh[n];
        __nv_bfloat16 h = __float2bfloat16(v);
        *(__nv_bfloat16*)(smc + B_HI + n * ROWB + 92 * 2) = h;
        *(__nv_bfloat16*)(smc + B_LO + n * ROWB + 92 * 2) =
            __float2bfloat16(v - __bfloat162float(h));
    }
    if (tid < M_TILE) {
        *(__nv_bfloat16*)(smc + A0_HI + tid * ROWB + 92 * 2) = __float2bfloat16(1.0f);
        *(__nv_bfloat16*)(smc + A1_HI + tid * ROWB + 92 * 2) = __float2bfloat16(1.0f);
    }
    for (int i = tid; i < O_DIM * H_DIM; i += NTHREADS) Wout_s[i] = W_out[i];
    if (tid < O_DIM) bout_s[tid] = b_out[tid];
    __syncthreads();

    // warp tiling: wm (0..7) rows [16wm,16wm+16); wn (0..1) units [32wn,32wn+32)
    const int wm = wid & 7;
    const int wn = wid >> 3;
    const int lg = lane >> 3, lr = lane & 7;

    const int a_row_off = ((lg & 1) * 8 + lr);
    const int a_k_off   = (lg >> 1) * 8;
    const int b_n_off   = ((lg >> 1) * 8 + lr);
    const int b_k_off   = (lg & 1) * 8;

    float cs[16];
#pragma unroll
    for (int i = 0; i < 16; ++i) cs[i] = 0.0f;

    // pair-local x staging: pair wm stages its own rows [16wm, 16wm+16).
    // tp = lane + 32*wn in 0..63; threads tp<32: row = 16wm + tp>>1, half = tp&1.
    const int tp     = lane + 32 * wn;
    const bool xactive = (tp < 32);
    const int xrow   = wm * 16 + (tp >> 1);
    const int xhalf  = tp & 1;
    const float* xbase = x + (size_t)(b0 + xrow) * (T_STEPS * I_DIM) + xhalf * 14;

    const int ep_row_base = wm * 16 + (lane >> 2);
    const int ep_col_base = wn * 32 + 2 * (lane & 3);

    float2 xpre[7];
    if (xactive) {
        const float2* xp = (const float2*)xbase;
#pragma unroll
        for (int j = 0; j < 7; ++j) xpre[j] = xp[j];
    }

    for (int t = 0; t < T_STEPS; ++t) {
        const uint32_t curHI = sb + ((t & 1) ? A1_HI : A0_HI);
        const uint32_t curLO = sb + ((t & 1) ? A1_LO : A0_LO);
        const uint32_t nxtHI = sb + ((t & 1) ? A0_HI : A1_HI);
        const uint32_t nxtLO = sb + ((t & 1) ? A0_LO : A1_LO);

        if (xactive) {
            const uint32_t rbase = (uint32_t)xrow * ROWB + (64 + xhalf * 14) * 2;
#pragma unroll
            for (int j = 0; j < 7; ++j) {
                float2 v = xpre[j];
                __nv_bfloat16 h0 = __float2bfloat16(v.x), h1 = __float2bfloat16(v.y);
                *(uint32_t*)(smc + (curHI - sb) + rbase + 4 * j) =
                    (uint32_t)__bfloat16_as_ushort(h0) | ((uint32_t)__bfloat16_as_ushort(h1) << 16);
                *(uint32_t*)(smc + (curLO - sb) + rbase + 4 * j) =
                    pack_bf16x2(v.x - __bfloat162float(h0), v.y - __bfloat162float(h1));
            }
            if (t + 1 < T_STEPS) {
                const float2* xp = (const float2*)(xbase + (t + 1) * I_DIM);
#pragma unroll
                for (int j = 0; j < 7; ++j) xpre[j] = xp[j];
            }
        }
        PAIR_BAR(wm);   // pair-scope: h(prev) + x(t) for rows of this wm visible

        // ---- two n-half phases ----
#pragma unroll
        for (int uh = 0; uh < 2; ++uh) {
            float acc[2][4][4];
#pragma unroll
            for (int u2 = 0; u2 < 2; ++u2)
#pragma unroll
                for (int g = 0; g < 4; ++g)
#pragma unroll
                    for (int r = 0; r < 4; ++r) acc[u2][g][r] = 0.0f;

#pragma unroll
            for (int ks = 0; ks < 6; ++ks) {
                const int k0 = ks * 16;
                uint32_t ah[4], al[4];
                {
                    uint32_t off = (uint32_t)(wm * 16 + a_row_off) * ROWB
                                 + (uint32_t)(k0 + a_k_off) * 2;
                    LDSM_X4(ah, curHI + off);
                    LDSM_X4(al, curLO + off);
                }
#pragma unroll
                for (int g = 0; g < 4; ++g) {
                    uint32_t bh[4], bl[4];
                    uint32_t off = (uint32_t)(g * 64 + wn * 32 + uh * 16 + b_n_off) * ROWB
                                 + (uint32_t)(k0 + b_k_off) * 2;
                    LDSM_X4(bh, sb + B_HI + off);
                    LDSM_X4(bl, sb + B_LO + off);
#pragma unroll
                    for (int u2 = 0; u2 < 2; ++u2) {
                        MMA16816(acc[u2][g], ah, bh[u2 * 2], bh[u2 * 2 + 1]);
                        MMA16816(acc[u2][g], ah, bl[u2 * 2], bl[u2 * 2 + 1]);
                        MMA16816(acc[u2][g], al, bh[u2 * 2], bh[u2 * 2 + 1]);
                    }
                }
            }

            // ---- epilogue ----
#pragma unroll
            for (int rh = 0; rh < 2; ++rh)
#pragma unroll
                for (int u2 = 0; u2 < 2; ++u2) {
                    const int uj = uh * 2 + u2;
                    float hv[2];
#pragma unroll
                    for (int e = 0; e < 2; ++e) {
                        const int r = rh * 2 + e;
                        float ig = siga(acc[u2][0][r]);
                        float fg = siga(acc[u2][1][r]);
                        float gg = tanha(acc[u2][2][r]);
                        float og = siga(acc[u2][3][r]);
                        const int ci = (rh * 4 + uj) * 2 + e;
                        float cn = fg * cs[ci] + ig * gg;
                        cs[ci] = cn;
                        hv[e] = og * tanha(cn);
                    }
                    __nv_bfloat16 h0 = __float2bfloat16(hv[0]);
                    __nv_bfloat16 h1 = __float2bfloat16(hv[1]);
                    const uint32_t off =
                        (uint32_t)(ep_row_base + rh * 8) * ROWB
                      + (uint32_t)(ep_col_base + uj * 8) * 2;
                    *(uint32_t*)(smc + (nxtHI - sb) + off) =
                        (uint32_t)__bfloat16_as_ushort(h0) |
                        ((uint32_t)__bfloat16_as_ushort(h1) << 16);
                    *(uint32_t*)(smc + (nxtLO - sb) + off) =
                        pack_bf16x2(hv[0] - __bfloat162float(h0),
                                    hv[1] - __bfloat162float(h1));
                }
        }
    }
    __syncthreads();   // all pairs done; final h (buffer 0, T even) visible

    // ---- output projection: 4 partials per row ----
    float* part = (float*)(smc + B_LO);
    {
        const int q = tid >> 7, r2 = tid & 127;
        float acc[O_DIM];
#pragma unroll
        for (int o = 0; o < O_DIM; ++o) acc[o] = 0.0f;
#pragma unroll
        for (int j = 0; j < 16; ++j) {
            const int u = q * 16 + j;
            float hv = __bfloat162float(*(__nv_bfloat16*)(smc + A0_HI + r2 * ROWB + u * 2))
                     + __bfloat162float(*(__nv_bfloat16*)(smc + A0_LO + r2 * ROWB + u * 2));
#pragma unroll
            for (int o = 0; o < O_DIM; ++o)
                acc[o] = fmaf(hv, Wout_s[o * H_DIM + u], acc[o]);
        }
        __syncthreads();
#pragma unroll
        for (int o = 0; o < O_DIM; ++o)
            part[(q * M_TILE + r2) * O_DIM + o] = acc[o];
    }
    __syncthreads();
    for (int idx = tid; idx < M_TILE * O_DIM; idx += NTHREADS) {
        int r = idx / O_DIM, o = idx % O_DIM;
        out[(size_t)(b0 + r) * O_DIM + o] =
            part[r * O_DIM + o] + part[(M_TILE + r) * O_DIM + o] +
            part[(2 * M_TILE + r) * O_DIM + o] + part[(3 * M_TILE + r) * O_DIM + o] +
            bout_s[o];
    }
}

extern "C" void kernel_launch(void* const* d_in, const int* in_sizes, int n_in,
                              void* d_out, int out_size)
{
    const float* x     = (const float*)d_in[0];
    const float* W_ih  = (const float*)d_in[1];
    const float* W_hh  = (const float*)d_in[2];
    const float* b_ih  = (const float*)d_in[3];
    const float* b_hh  = (const float*)d_in[4];
    const float* W_out = (const float*)d_in[5];
    const float* b_out = (const float*)d_in[6];
    float* out = (float*)d_out;

    cudaFuncSetAttribute(lstm_mma_kernel,
                         cudaFuncAttributeMaxDynamicSharedMemorySize, SMEM_TOTAL);

    lstm_mma_kernel<<<B_TOTAL / M_TILE, NTHREADS, SMEM_TOTAL>>>(
        x, W_ih, W_hh, b_ih, b_hh, W_out, b_out, out);
}

// round 11
// speedup vs baseline: 5.3362x; 1.2069x over previous
#include <cuda_runtime.h>
#include <cuda_fp16.h>
#include <cstdint>

// LSTM via mma.sync (HMMA, fp16). B=65536, T=28, I=28, H=64, O=10.
// R11: fp16 operands with precision-targeted split:
//   pass1 Ah@Bh (K=96), pass2 Al@Bh (K=64, h residual), pass3 Ah@Bl (K=64,
//   W_hh residual). W_ih/x/bias residuals dropped (one-shot, ~1e-4 abs).
// MMA count x0.78 vs R10. Structure = R10: 512 thr, 8m x 2n warps, pairwise
// named barriers, h double-buffered, x prefetch pipelined.

#define T_STEPS  28
#define I_DIM    28
#define H_DIM    64
#define O_DIM    10
#define M_TILE   128
#define NTHREADS 512
#define B_TOTAL  65536

#define KSTRIDE  104
#define ROWB     (KSTRIDE * 2)        // 208 bytes

#define A0_HI 0
#define A0_LO (A0_HI + M_TILE * ROWB)
#define A1_HI (A0_LO + M_TILE * ROWB)
#define A1_LO (A1_HI + M_TILE * ROWB)
#define B_HI  (A1_LO + M_TILE * ROWB)
#define B_LO  (B_HI + 256 * ROWB)
#define WOUT  (B_LO + 256 * ROWB)
#define BOUT  (WOUT + O_DIM * H_DIM * 4)
#define SMEM_TOTAL (BOUT + 64)

__device__ __forceinline__ uint32_t smem_u32(const void* p) {
    uint32_t a;
    asm("{ .reg .u64 t; cvta.to.shared.u64 t, %1; cvt.u32.u64 %0, t; }" : "=r"(a) : "l"(p));
    return a;
}

#define LDSM_X4(r, addr)                                                     \
    asm volatile("ldmatrix.sync.aligned.m8n8.x4.shared.b16 {%0,%1,%2,%3}, [%4];" \
                 : "=r"((r)[0]), "=r"((r)[1]), "=r"((r)[2]), "=r"((r)[3])    \
                 : "r"(addr))

#define MMA16816(d, a, b0v, b1v)                                             \
    asm volatile("mma.sync.aligned.m16n8k16.row.col.f32.f16.f16.f32 "       \
                 "{%0,%1,%2,%3},{%4,%5,%6,%7},{%8,%9},{%0,%1,%2,%3};"        \
                 : "+f"((d)[0]), "+f"((d)[1]), "+f"((d)[2]), "+f"((d)[3])    \
                 : "r"((a)[0]), "r"((a)[1]), "r"((a)[2]), "r"((a)[3]),       \
                   "r"(b0v), "r"(b1v))

#define PAIR_BAR(id)                                                          \
    asm volatile("bar.sync %0, 64;" :: "r"((id) + 1) : "memory")

__device__ __forceinline__ float tanha(float x) {
    float r; asm("tanh.approx.f32 %0, %1;" : "=f"(r) : "f"(x)); return r;
}
__device__ __forceinline__ float siga(float x) {
    return fmaf(tanha(0.5f * x), 0.5f, 0.5f);
}
__device__ __forceinline__ uint32_t pack_f16x2(float a, float b) {
    __half ha = __float2half_rn(a), hb = __float2half_rn(b);
    return (uint32_t)__half_as_ushort(ha) | ((uint32_t)__half_as_ushort(hb) << 16);
}

__global__ __launch_bounds__(NTHREADS, 1)
void lstm_mma_kernel(const float* __restrict__ x,
                     const float* __restrict__ W_ih,
                     const float* __restrict__ W_hh,
                     const float* __restrict__ b_ih,
                     const float* __restrict__ b_hh,
                     const float* __restrict__ W_out,
                     const float* __restrict__ b_out,
                     float* __restrict__ out)
{
    extern __shared__ char smc[];
    const uint32_t sb = smem_u32(smc);
    const int tid  = threadIdx.x;
    const int wid  = tid >> 5;
    const int lane = tid & 31;
    const int b0   = blockIdx.x * M_TILE;

    float* Wout_s = (float*)(smc + WOUT);
    float* bout_s = (float*)(smc + BOUT);

    // ---- zero A/B tiles ----
    for (int i = tid; i < (B_LO + 256 * ROWB) / 4; i += NTHREADS)
        ((uint32_t*)smc)[i] = 0u;
    __syncthreads();

    // B_HI = fp16(W); B_LO = fp16 residual for W_hh block (cols 0..63) only.
    for (int idx = tid; idx < 256 * H_DIM; idx += NTHREADS) {
        int n = idx >> 6, k = idx & 63;
        float v = W_hh[idx];
        __half h = __float2half_rn(v);
        *(__half*)(smc + B_HI + n * ROWB + k * 2) = h;
        *(__half*)(smc + B_LO + n * ROWB + k * 2) =
            __float2half_rn(v - __half2float(h));
    }
    for (int idx = tid; idx < 256 * I_DIM; idx += NTHREADS) {
        int n = idx / I_DIM, i = idx % I_DIM;
        *(__half*)(smc + B_HI + n * ROWB + (64 + i) * 2) = __float2half_rn(W_ih[idx]);
    }
    for (int n = tid; n < 256; n += NTHREADS)
        *(__half*)(smc + B_HI + n * ROWB + 92 * 2) = __float2half_rn(b_ih[n] + b_hh[n]);
    if (tid < M_TILE) {
        *(__half*)(smc + A0_HI + tid * ROWB + 92 * 2) = __float2half_rn(1.0f);
        *(__half*)(smc + A1_HI + tid * ROWB + 92 * 2) = __float2half_rn(1.0f);
    }
    for (int i = tid; i < O_DIM * H_DIM; i += NTHREADS) Wout_s[i] = W_out[i];
    if (tid < O_DIM) bout_s[tid] = b_out[tid];
    __syncthreads();

    // warp tiling: wm (0..7) rows [16wm,16wm+16); wn (0..1) units [32wn,32wn+32)
    const int wm = wid & 7;
    const int wn = wid >> 3;
    const int lg = lane >> 3, lr = lane & 7;

    const int a_row_off = ((lg & 1) * 8 + lr);
    const int a_k_off   = (lg >> 1) * 8;
    const int b_n_off   = ((lg >> 1) * 8 + lr);
    const int b_k_off   = (lg & 1) * 8;

    float cs[16];
#pragma unroll
    for (int i = 0; i < 16; ++i) cs[i] = 0.0f;

    // pair-local x staging (rows of this wm)
    const int tp     = lane + 32 * wn;
    const bool xactive = (tp < 32);
    const int xrow   = wm * 16 + (tp >> 1);
    const int xhalf  = tp & 1;
    const float* xbase = x + (size_t)(b0 + xrow) * (T_STEPS * I_DIM) + xhalf * 14;

    const int ep_row_base = wm * 16 + (lane >> 2);
    const int ep_col_base = wn * 32 + 2 * (lane & 3);

    float2 xpre[7];
    if (xactive) {
        const float2* xp = (const float2*)xbase;
#pragma unroll
        for (int j = 0; j < 7; ++j) xpre[j] = xp[j];
    }

    for (int t = 0; t < T_STEPS; ++t) {
        const uint32_t curHI = sb + ((t & 1) ? A1_HI : A0_HI);
        const uint32_t curLO = sb + ((t & 1) ? A1_LO : A0_LO);
        const uint32_t nxtHI = sb + ((t & 1) ? A0_HI : A1_HI);
        const uint32_t nxtLO = sb + ((t & 1) ? A0_LO : A1_LO);

        if (xactive) {
            const uint32_t rbase = (uint32_t)xrow * ROWB + (64 + xhalf * 14) * 2;
#pragma unroll
            for (int j = 0; j < 7; ++j) {
                float2 v = xpre[j];
                *(uint32_t*)(smc + (curHI - sb) + rbase + 4 * j) = pack_f16x2(v.x, v.y);
            }
            if (t + 1 < T_STEPS) {
                const float2* xp = (const float2*)(xbase + (t + 1) * I_DIM);
#pragma unroll
                for (int j = 0; j < 7; ++j) xpre[j] = xp[j];
            }
        }
        PAIR_BAR(wm);

        // ---- two n-half phases ----
#pragma unroll
        for (int uh = 0; uh < 2; ++uh) {
            float acc[2][4][4];
#pragma unroll
            for (int u2 = 0; u2 < 2; ++u2)
#pragma unroll
                for (int g = 0; g < 4; ++g)
#pragma unroll
                    for (int r = 0; r < 4; ++r) acc[u2][g][r] = 0.0f;

#pragma unroll
            for (int ks = 0; ks < 6; ++ks) {
                const int k0 = ks * 16;
                const bool lo = (ks < 4);      // compile-time under unroll
                uint32_t ah[4], al[4];
                {
                    uint32_t off = (uint32_t)(wm * 16 + a_row_off) * ROWB
                                 + (uint32_t)(k0 + a_k_off) * 2;
                    LDSM_X4(ah, curHI + off);
                    if (lo) LDSM_X4(al, curLO + off);
                }
#pragma unroll
                for (int g = 0; g < 4; ++g) {
                    uint32_t off = (uint32_t)(g * 64 + wn * 32 + uh * 16 + b_n_off) * ROWB
                                 + (uint32_t)(k0 + b_k_off) * 2;
                    uint32_t bh[4];
                    LDSM_X4(bh, sb + B_HI + off);
#pragma unroll
                    for (int u2 = 0; u2 < 2; ++u2)
                        MMA16816(acc[u2][g], ah, bh[u2 * 2], bh[u2 * 2 + 1]);
                    if (lo) {
                        uint32_t bl[4];
                        LDSM_X4(bl, sb + B_LO + off);
#pragma unroll
                        for (int u2 = 0; u2 < 2; ++u2) {
                            MMA16816(acc[u2][g], ah, bl[u2 * 2], bl[u2 * 2 + 1]);
                            MMA16816(acc[u2][g], al, bh[u2 * 2], bh[u2 * 2 + 1]);
                        }
                    }
                }
            }

            // ---- epilogue ----
#pragma unroll
            for (int rh = 0; rh < 2; ++rh)
#pragma unroll
                for (int u2 = 0; u2 < 2; ++u2) {
                    const int uj = uh * 2 + u2;
                    float hv[2];
#pragma unroll
                    for (int e = 0; e < 2; ++e) {
                        const int r = rh * 2 + e;
                        float ig = siga(acc[u2][0][r]);
                        float fg = siga(acc[u2][1][r]);
                        float gg = tanha(acc[u2][2][r]);
                        float og = siga(acc[u2][3][r]);
                        const int ci = (rh * 4 + uj) * 2 + e;
                        float cn = fg * cs[ci] + ig * gg;
                        cs[ci] = cn;
                        hv[e] = og * tanha(cn);
                    }
                    __half h0 = __float2half_rn(hv[0]);
                    __half h1 = __float2half_rn(hv[1]);
                    const uint32_t off =
                        (uint32_t)(ep_row_base + rh * 8) * ROWB
                      + (uint32_t)(ep_col_base + uj * 8) * 2;
                    *(uint32_t*)(smc + (nxtHI - sb) + off) =
                        (uint32_t)__half_as_ushort(h0) |
                        ((uint32_t)__half_as_ushort(h1) << 16);
                    *(uint32_t*)(smc + (nxtLO - sb) + off) =
                        pack_f16x2(hv[0] - __half2float(h0),
                                   hv[1] - __half2float(h1));
                }
        }
    }
    __syncthreads();   // all pairs done; final h (buffer 0, T even) visible

    // ---- output projection: 4 partials per row (scratch in A1 region) ----
    float* part = (float*)(smc + A1_HI);
    {
        const int q = tid >> 7, r2 = tid & 127;
        float acc[O_DIM];
#pragma unroll
        for (int o = 0; o < O_DIM; ++o) acc[o] = 0.0f;
#pragma unroll
        for (int j = 0; j < 16; ++j) {
            const int u = q * 16 + j;
            float hv = __half2float(*(__half*)(smc + A0_HI + r2 * ROWB + u * 2))
                     + __half2float(*(__half*)(smc + A0_LO + r2 * ROWB + u * 2));
#pragma unroll
            for (int o = 0; o < O_DIM; ++o)
                acc[o] = fmaf(hv, Wout_s[o * H_DIM + u], acc[o]);
        }
        __syncthreads();
#pragma unroll
        for (int o = 0; o < O_DIM; ++o)
            part[(q * M_TILE + r2) * O_DIM + o] = acc[o];
    }
    __syncthreads();
    for (int idx = tid; idx < M_TILE * O_DIM; idx += NTHREADS) {
        int r = idx / O_DIM, o = idx % O_DIM;
        out[(size_t)(b0 + r) * O_DIM + o] =
            part[r * O_DIM + o] + part[(M_TILE + r) * O_DIM + o] +
            part[(2 * M_TILE + r) * O_DIM + o] + part[(3 * M_TILE + r) * O_DIM + o] +
            bout_s[o];
    }
}

extern "C" void kernel_launch(void* const* d_in, const int* in_sizes, int n_in,
                              void* d_out, int out_size)
{
    const float* x     = (const float*)d_in[0];
    const float* W_ih  = (const float*)d_in[1];
    const float* W_hh  = (const float*)d_in[2];
    const float* b_ih  = (const float*)d_in[3];
    const float* b_hh  = (const float*)d_in[4];
    const float* W_out = (const float*)d_in[5];
    const float* b_out = (const float*)d_in[6];
    float* out = (float*)d_out;

    cudaFuncSetAttribute(lstm_mma_kernel,
                         cudaFuncAttributeMaxDynamicSharedMemorySize, SMEM_TOTAL);

    lstm_mma_kernel<<<B_TOTAL / M_TILE, NTHREADS, SMEM_TOTAL>>>(
        x, W_ih, W_hh, b_ih, b_hh, W_out, b_out, out);
}